// round 1
// baseline (speedup 1.0000x reference)
#include <cuda_runtime.h>
#include <math.h>

#define Bq 64
#define Tq 512
#define Iq 512
#define Hq 1024
#define Oq 512
#define Gq (3*Hq)

// -------- scratch (device globals: allocation-free rule) --------
__device__ float g_xp[(size_t)Tq * Bq * Gq];   // [t][b][3H] gate pre-activations (input side)
__device__ float g_hs[(size_t)Bq * Tq * Hq];   // [b][t][H] hidden states
__device__ float g_hA[Bq * Hq];
__device__ float g_hB[Bq * Hq];
__device__ unsigned g_cnt = 0;
__device__ volatile unsigned g_gen = 0;

// ============================================================================
// Generic tiled fp32 GEMM with bias: C[m][n] = sum_k A[m][k]*Bw[n][k] + bias[n]
// Block tile 128x64, K-tile 16, 256 threads, 8x4 register tile.
// MODE 1: A rows indexed as m = t*64 + b over inputs[b][t][:]  (x_proj GEMM)
// MODE 0: A row m at A + m*K                                   (output GEMM)
// Dims must divide tiles exactly (they do for this problem).
// ============================================================================
template <int MODE>
__global__ __launch_bounds__(256) void gemm_bias_kernel(
    const float* __restrict__ A, const float* __restrict__ Bw,
    const float* __restrict__ bias, float* __restrict__ C,
    int M, int N, int K)
{
    __shared__ __align__(16) float As[16 * 132];
    __shared__ __align__(16) float Bs[16 * 68];

    const int tid = threadIdx.x;
    const int m0 = blockIdx.y * 128;
    const int n0 = blockIdx.x * 64;
    const int lk = tid & 15;   // k lane for loads
    const int lr = tid >> 4;   // row lane for loads (0..15)
    const int mg = tid >> 4;   // compute: m group (0..15)
    const int ng = tid & 15;   // compute: n group (0..15)

    float acc[8][4];
#pragma unroll
    for (int i = 0; i < 8; i++)
#pragma unroll
        for (int j = 0; j < 4; j++) acc[i][j] = 0.0f;

    size_t arow[8];
#pragma unroll
    for (int p = 0; p < 8; p++) {
        const int m = m0 + lr + p * 16;
        if (MODE == 1) {
            // m = t*64 + b ; inputs[b][t][:] at ((b*T + t)*I)
            arow[p] = ((size_t)(m & 63) * Tq + (size_t)(m >> 6)) * Iq;
        } else {
            arow[p] = (size_t)m * (size_t)K;
        }
    }
    size_t brow[4];
#pragma unroll
    for (int p = 0; p < 4; p++) brow[p] = (size_t)(n0 + lr + p * 16) * (size_t)K;

    for (int k0 = 0; k0 < K; k0 += 16) {
#pragma unroll
        for (int p = 0; p < 8; p++)
            As[lk * 132 + lr + p * 16] = A[arow[p] + k0 + lk];
#pragma unroll
        for (int p = 0; p < 4; p++)
            Bs[lk * 68 + lr + p * 16] = Bw[brow[p] + k0 + lk];
        __syncthreads();

#pragma unroll
        for (int k = 0; k < 16; k++) {
            const float4 a0 = *(const float4*)&As[k * 132 + mg * 8];
            const float4 a1 = *(const float4*)&As[k * 132 + mg * 8 + 4];
            const float4 b0 = *(const float4*)&Bs[k * 68 + ng * 4];
            const float av[8] = {a0.x, a0.y, a0.z, a0.w, a1.x, a1.y, a1.z, a1.w};
            const float bv[4] = {b0.x, b0.y, b0.z, b0.w};
#pragma unroll
            for (int i = 0; i < 8; i++)
#pragma unroll
                for (int j = 0; j < 4; j++)
                    acc[i][j] = fmaf(av[i], bv[j], acc[i][j]);
        }
        __syncthreads();
    }

    const float4 bb = *(const float4*)&bias[n0 + ng * 4];
#pragma unroll
    for (int i = 0; i < 8; i++) {
        const int m = m0 + mg * 8 + i;
        float4 o;
        o.x = acc[i][0] + bb.x;
        o.y = acc[i][1] + bb.y;
        o.z = acc[i][2] + bb.z;
        o.w = acc[i][3] + bb.w;
        *(float4*)&C[(size_t)m * N + n0 + ng * 4] = o;
    }
}

// ============================================================================
// Persistent recurrent kernel. 128 blocks x 256 threads, all co-resident.
// Block nb owns h-columns [nb*8, nb*8+8), computes all 3 gates for all 64 b.
// w_hh chunk (24 rows x 1024) lives in SMEM for the whole kernel.
// Thread decomposition: kz = tid>>6 splits K=1024 into 4 ranges of 256;
// within a kz-group of 64 threads: mg = 8 b's each, ng = local h-column.
// ============================================================================
#define REC_NBLK 128
#define WS_FLOATS (1024 * 25)          // w_s[k*25 + r], r = g*8 + j (conflict-free reads)
#define HS_FLOATS (4 * 64 * 68)        // per-kz h staging [kk][b], pitch 68 (float4 reads)
#define RED_FLOATS (3 * 64 * 24)       // partial-sum exchange
#define REC_SMEM ((WS_FLOATS + HS_FLOATS + RED_FLOATS) * 4)

__global__ __launch_bounds__(256, 1) void gru_rec_kernel(
    const float* __restrict__ xp, const float* __restrict__ h0,
    const float* __restrict__ w_hh, const float* __restrict__ b_hh,
    float* __restrict__ hs)
{
    extern __shared__ float sm[];
    float* w_s = sm;                       // [1024][25]
    float* h_s = sm + WS_FLOATS;           // [4][64][68]
    float* red_s = h_s + HS_FLOATS;        // [3][64][24]

    const int tid = threadIdx.x;
    const int kz = tid >> 6;       // 0..3  K-split group
    const int t64 = tid & 63;
    const int mg = t64 >> 3;       // 0..7 -> b = mg*8 + i
    const int ng = t64 & 7;        // local h column
    const int hc = blockIdx.x * 8 + ng;

    // Preload weight chunk once for all 512 steps.
    for (int r = 0; r < 24; r++) {
        const int g = r >> 3, j = r & 7;
        const float* src = w_hh + ((size_t)g * Hq + blockIdx.x * 8 + j) * Hq;
        for (int k = tid; k < Hq; k += 256) w_s[k * 25 + r] = src[k];
    }
    const float bh_r = b_hh[hc];
    const float bh_z = b_hh[Hq + hc];
    const float bh_n = b_hh[2 * Hq + hc];
    __syncthreads();

    float* my_hs = h_s + kz * (64 * 68);
    const int kbase = kz * 256;

    for (int t = 0; t < Tq; t++) {
        const float* h_old = (t == 0) ? h0 : ((t & 1) ? g_hB : g_hA);
        float* h_new = (t & 1) ? g_hA : g_hB;

        float acc[8][3];
#pragma unroll
        for (int i = 0; i < 8; i++) { acc[i][0] = 0.f; acc[i][1] = 0.f; acc[i][2] = 0.f; }

        for (int c = 0; c < 4; c++) {
            // stage h_old[:, k] for this kz-group's K-chunk (L2 reads, L1 bypass)
            const int k = kbase + c * 64 + t64;
#pragma unroll
            for (int bb = 0; bb < 64; bb += 16) {
                float tmp[16];
#pragma unroll
                for (int i = 0; i < 16; i++)
                    tmp[i] = __ldcg(h_old + (size_t)(bb + i) * Hq + k);
#pragma unroll
                for (int i = 0; i < 16; i++)
                    my_hs[t64 * 68 + bb + i] = tmp[i];
            }
            __syncthreads();

            const int kc0 = kbase + c * 64;
#pragma unroll 4
            for (int kk = 0; kk < 64; kk++) {
                const int k2 = kc0 + kk;
                const float wr = w_s[k2 * 25 + ng];
                const float wz = w_s[k2 * 25 + 8 + ng];
                const float wn = w_s[k2 * 25 + 16 + ng];
                const float4 h0v = *(const float4*)&my_hs[kk * 68 + mg * 8];
                const float4 h1v = *(const float4*)&my_hs[kk * 68 + mg * 8 + 4];
                const float hv[8] = {h0v.x, h0v.y, h0v.z, h0v.w,
                                     h1v.x, h1v.y, h1v.z, h1v.w};
#pragma unroll
                for (int i = 0; i < 8; i++) {
                    acc[i][0] = fmaf(hv[i], wr, acc[i][0]);
                    acc[i][1] = fmaf(hv[i], wz, acc[i][1]);
                    acc[i][2] = fmaf(hv[i], wn, acc[i][2]);
                }
            }
            __syncthreads();
        }

        // K-split reduction into kz==0
        if (kz > 0) {
            float* dst = red_s + ((kz - 1) * 64 + t64) * 24;
#pragma unroll
            for (int i = 0; i < 8; i++) {
                dst[i * 3 + 0] = acc[i][0];
                dst[i * 3 + 1] = acc[i][1];
                dst[i * 3 + 2] = acc[i][2];
            }
        }
        __syncthreads();

        if (kz == 0) {
#pragma unroll
            for (int z = 0; z < 3; z++) {
                const float* src = red_s + (z * 64 + t64) * 24;
#pragma unroll
                for (int i = 0; i < 8; i++) {
                    acc[i][0] += src[i * 3 + 0];
                    acc[i][1] += src[i * 3 + 1];
                    acc[i][2] += src[i * 3 + 2];
                }
            }
            const float* xpt = xp + (size_t)t * (Bq * Gq);
#pragma unroll
            for (int i = 0; i < 8; i++) {
                const int b = mg * 8 + i;
                const float* xpb = xpt + (size_t)b * Gq + hc;
                const float xr = xpb[0];
                const float xz = xpb[Hq];
                const float xn = xpb[2 * Hq];
                const float rr = 1.0f / (1.0f + __expf(-(xr + acc[i][0] + bh_r)));
                const float zz = 1.0f / (1.0f + __expf(-(xz + acc[i][1] + bh_z)));
                const float nn = tanhf(xn + rr * (acc[i][2] + bh_n));
                const float hp = __ldcg(h_old + (size_t)b * Hq + hc);
                const float hv = (1.0f - zz) * nn + zz * hp;
                h_new[(size_t)b * Hq + hc] = hv;
                hs[((size_t)b * Tq + t) * Hq + hc] = hv;
            }
        }

        // ---- software grid barrier (all 128 blocks resident) ----
        __threadfence();
        __syncthreads();
        if (tid == 0) {
            const unsigned g = g_gen;
            if (atomicAdd(&g_cnt, 1) == (unsigned)(REC_NBLK - 1)) {
                g_cnt = 0;
                __threadfence();
                g_gen = g + 1;
            } else {
                while (g_gen == g) { }
            }
        }
        __syncthreads();
    }
}

// Copy final hidden state hs[:, T-1, :] into the tail of d_out.
__global__ void copy_hlast_kernel(const float* __restrict__ hs, float* __restrict__ out)
{
    const int idx = blockIdx.x * 256 + threadIdx.x;
    if (idx < Bq * Hq) {
        const int b = idx >> 10;
        const int h = idx & 1023;
        out[idx] = hs[((size_t)b * Tq + (Tq - 1)) * Hq + h];
    }
}

// ============================================================================
extern "C" void kernel_launch(void* const* d_in, const int* in_sizes, int n_in,
                              void* d_out, int out_size)
{
    const float* inputs = (const float*)d_in[0];
    const float* h0     = (const float*)d_in[1];
    const float* w_ih   = (const float*)d_in[2];
    const float* w_hh   = (const float*)d_in[3];
    const float* b_ih   = (const float*)d_in[4];
    const float* b_hh   = (const float*)d_in[5];
    const float* w_out  = (const float*)d_in[6];
    const float* b_out  = (const float*)d_in[7];
    float* out = (float*)d_out;

    float *xp, *hs;
    cudaGetSymbolAddress((void**)&xp, g_xp);
    cudaGetSymbolAddress((void**)&hs, g_hs);

    // K1: x_proj = inputs @ w_ih^T + b_ih  -> xp[t][b][3H]
    {
        dim3 grid(Gq / 64, (Tq * Bq) / 128);
        gemm_bias_kernel<1><<<grid, 256>>>(inputs, w_ih, b_ih, xp, Tq * Bq, Gq, Iq);
    }

    // K2: persistent GRU recurrence -> hs[b][t][H]
    cudaFuncSetAttribute(gru_rec_kernel, cudaFuncAttributeMaxDynamicSharedMemorySize, REC_SMEM);
    gru_rec_kernel<<<REC_NBLK, 256, REC_SMEM>>>(xp, h0, w_hh, b_hh, hs);

    // K3: out = hs @ w_out^T + b_out -> d_out[0 : B*T*O]
    {
        dim3 grid(Oq / 64, (Bq * Tq) / 128);
        gemm_bias_kernel<0><<<grid, 256>>>(hs, w_out, b_out, out, Bq * Tq, Oq, Hq);
    }

    // K4: h_last tail
    copy_hlast_kernel<<<(Bq * Hq) / 256, 256>>>(hs, out + (size_t)Bq * Tq * Oq);
}

// round 2
// speedup vs baseline: 1.0431x; 1.0431x over previous
#include <cuda_runtime.h>
#include <math.h>

#define Bq 64
#define Tq 512
#define Iq 512
#define Hq 1024
#define Oq 512
#define Gq 3072

// -------- scratch (device globals: allocation-free rule) --------
__device__ float g_xp[(size_t)Tq * Bq * Gq];   // [t][b][3H]
__device__ float g_hs[(size_t)Bq * Tq * Hq];   // [b][t][H]
__device__ float g_hA[Bq * Hq];
__device__ float g_hB[Bq * Hq];
__device__ volatile unsigned g_flag[64 * 32];  // one cacheline-ish apart
__device__ volatile unsigned g_gen = 0;

// -------- tf32 helpers --------
__device__ __forceinline__ unsigned f2tf(float f) {
    unsigned u; asm("cvt.rna.tf32.f32 %0, %1;" : "=r"(u) : "f"(f)); return u;
}
__device__ __forceinline__ void mma_tf32(
    float& d0, float& d1, float& d2, float& d3,
    unsigned a0, unsigned a1, unsigned a2, unsigned a3,
    unsigned b0, unsigned b1)
{
    asm volatile(
        "mma.sync.aligned.m16n8k8.row.col.f32.tf32.tf32.f32 "
        "{%0,%1,%2,%3},{%4,%5,%6,%7},{%8,%9},{%0,%1,%2,%3};"
        : "+f"(d0), "+f"(d1), "+f"(d2), "+f"(d3)
        : "r"(a0), "r"(a1), "r"(a2), "r"(a3), "r"(b0), "r"(b1));
}

// ============================================================================
// MMA GEMM: C[m][n] = sum_k A[m][k] * Bw[n][k] + bias[n]
// Block tile 128(M) x 64(N), k-tile 32, 256 threads.
// Warp grid 4(m) x 2(n): warp tile 32x32 -> 2 m-tiles x 4 n-tiles.
// SMEM pair layout: {k=q, k=q+4} float2 -> every fragment is one LDS.64.
// MODE 1: A row m -> inputs[b=m&63][t=m>>6][:]   (x_proj GEMM)
// MODE 0: A row m at A + m*K                     (output GEMM)
// ============================================================================
template <int MODE>
__global__ __launch_bounds__(256) void mma_gemm(
    const float* __restrict__ A, const float* __restrict__ Bw,
    const float* __restrict__ bias, float* __restrict__ C,
    int N, int K)
{
    __shared__ __align__(16) uint2 As2[4 * 128 * 4];  // [k8][m][q]
    __shared__ __align__(16) uint2 Bs2[4 * 64 * 4];   // [k8][n][q]

    const int tid = threadIdx.x;
    const int m0 = blockIdx.y * 128, n0 = blockIdx.x * 64;
    const int lane = tid & 31, warp = tid >> 5;
    const int g = lane >> 2, q = lane & 3;
    const int wm = warp >> 1, wn = warp & 1;   // m offset wm*32, n offset wn*32

    // staging decomposition
    const int ak8 = tid & 3;
    int am[2]; am[0] = tid >> 2; am[1] = (tid >> 2) + 64;
    size_t arow[2];
#pragma unroll
    for (int i = 0; i < 2; i++) {
        const int m = m0 + am[i];
        arow[i] = (MODE == 1) ? ((size_t)(m & 63) * Tq + (size_t)(m >> 6)) * Iq
                              : (size_t)m * (size_t)K;
    }
    const int bn = tid >> 2;
    const size_t brow = (size_t)(n0 + bn) * (size_t)K;

    float acc[2][4][4];
#pragma unroll
    for (int mt = 0; mt < 2; mt++)
#pragma unroll
        for (int nt = 0; nt < 4; nt++)
#pragma unroll
            for (int e = 0; e < 4; e++) acc[mt][nt][e] = 0.0f;

    float4 pa[2][2], pb[2];
    // prefetch k0 = 0
#pragma unroll
    for (int i = 0; i < 2; i++) {
        pa[i][0] = __ldg((const float4*)(A + arow[i] + ak8 * 8));
        pa[i][1] = __ldg((const float4*)(A + arow[i] + ak8 * 8 + 4));
    }
    pb[0] = __ldg((const float4*)(Bw + brow + ak8 * 8));
    pb[1] = __ldg((const float4*)(Bw + brow + ak8 * 8 + 4));

    for (int k0 = 0; k0 < K; k0 += 32) {
        // store staged regs -> smem (pair layout)
#pragma unroll
        for (int i = 0; i < 2; i++) {
            uint2* dst = &As2[((size_t)ak8 * 128 + am[i]) * 4];
            dst[0] = make_uint2(f2tf(pa[i][0].x), f2tf(pa[i][1].x));
            dst[1] = make_uint2(f2tf(pa[i][0].y), f2tf(pa[i][1].y));
            dst[2] = make_uint2(f2tf(pa[i][0].z), f2tf(pa[i][1].z));
            dst[3] = make_uint2(f2tf(pa[i][0].w), f2tf(pa[i][1].w));
        }
        {
            uint2* dst = &Bs2[((size_t)ak8 * 64 + bn) * 4];
            dst[0] = make_uint2(f2tf(pb[0].x), f2tf(pb[1].x));
            dst[1] = make_uint2(f2tf(pb[0].y), f2tf(pb[1].y));
            dst[2] = make_uint2(f2tf(pb[0].z), f2tf(pb[1].z));
            dst[3] = make_uint2(f2tf(pb[0].w), f2tf(pb[1].w));
        }
        __syncthreads();

        if (k0 + 32 < K) {
#pragma unroll
            for (int i = 0; i < 2; i++) {
                pa[i][0] = __ldg((const float4*)(A + arow[i] + k0 + 32 + ak8 * 8));
                pa[i][1] = __ldg((const float4*)(A + arow[i] + k0 + 32 + ak8 * 8 + 4));
            }
            pb[0] = __ldg((const float4*)(Bw + brow + k0 + 32 + ak8 * 8));
            pb[1] = __ldg((const float4*)(Bw + brow + k0 + 32 + ak8 * 8 + 4));
        }

#pragma unroll
        for (int k8 = 0; k8 < 4; k8++) {
            uint2 a02[2], a13[2];
#pragma unroll
            for (int mt = 0; mt < 2; mt++) {
                a02[mt] = As2[((size_t)k8 * 128 + wm * 32 + mt * 16 + g) * 4 + q];
                a13[mt] = As2[((size_t)k8 * 128 + wm * 32 + mt * 16 + g + 8) * 4 + q];
            }
            uint2 bf[4];
#pragma unroll
            for (int nt = 0; nt < 4; nt++)
                bf[nt] = Bs2[((size_t)k8 * 64 + wn * 32 + nt * 8 + g) * 4 + q];
#pragma unroll
            for (int mt = 0; mt < 2; mt++)
#pragma unroll
                for (int nt = 0; nt < 4; nt++)
                    mma_tf32(acc[mt][nt][0], acc[mt][nt][1], acc[mt][nt][2], acc[mt][nt][3],
                             a02[mt].x, a13[mt].x, a02[mt].y, a13[mt].y,
                             bf[nt].x, bf[nt].y);
        }
        __syncthreads();
    }

    // epilogue
#pragma unroll
    for (int mt = 0; mt < 2; mt++) {
        const int mrow = m0 + wm * 32 + mt * 16 + g;
#pragma unroll
        for (int nt = 0; nt < 4; nt++) {
            const int col = n0 + wn * 32 + nt * 8 + 2 * q;
            const float2 bb = *(const float2*)&bias[col];
            float2 o0, o1;
            o0.x = acc[mt][nt][0] + bb.x; o0.y = acc[mt][nt][1] + bb.y;
            o1.x = acc[mt][nt][2] + bb.x; o1.y = acc[mt][nt][3] + bb.y;
            *(float2*)&C[(size_t)mrow * N + col] = o0;
            *(float2*)&C[(size_t)(mrow + 8) * N + col] = o1;
        }
    }
}

// ============================================================================
// Persistent GRU recurrence, tensor-core version.
// 64 blocks x 256 threads. Block owns 16 h-cols x 3 gates = 48 output cols.
// w_hh chunk resident in SMEM as tf32 pairs: [k8(128)][n(48)][q(4)] = 192KB.
// h streamed per step in 16 chunks of 64 k, double-buffered (2 x 16KB).
// mma orientation: m = batch(64), n = 48 cols, k = 1024.
// Warp grid 4(m) x 2(n): warp tile 16 x 24 (1 m-tile, 3 n-tiles).
// ============================================================================
#define NB2 64
#define WS2_U2 (128 * 48 * 4)
#define HS2_U2 (2 * 8 * 64 * 4)
#define K2_SMEM ((WS2_U2 + HS2_U2) * 8)   // 229376 B

__global__ __launch_bounds__(256, 1) void gru_rec_mma(
    const float* __restrict__ xp, const float* __restrict__ h0,
    const float* __restrict__ w_hh, const float* __restrict__ b_hh,
    float* __restrict__ hs)
{
    extern __shared__ uint2 sm2[];
    uint2* Ws2 = sm2;                       // [k8g][n][q]
    uint2* Hs2 = sm2 + WS2_U2;              // [buf][k8l][b][q]
    float* Cs  = (float*)(sm2 + WS2_U2);    // aliases h-buf0, used post-loop [64][50]

    const int tid = threadIdx.x;
    const int lane = tid & 31, warp = tid >> 5;
    const int g = lane >> 2, q = lane & 3;
    const int wm = warp >> 1, wn = warp & 1;
    const int hc0 = blockIdx.x * 16;

    // ---- preload resident weights (once) ----
    for (int idx = tid; idx < 128 * 48 * 4; idx += 256) {
        const int k8 = idx / 192;
        const int r = idx - k8 * 192;
        const int n = r >> 2, qq = r & 3;
        const float* src = w_hh + ((size_t)(n >> 4) * Hq + hc0 + (n & 15)) * Hq + k8 * 8 + qq;
        Ws2[idx] = make_uint2(f2tf(src[0]), f2tf(src[4]));
    }
    const int jj = tid & 15;
    const float bhr = b_hh[hc0 + jj];
    const float bhz = b_hh[Hq + hc0 + jj];
    const float bhn = b_hh[2 * Hq + hc0 + jj];

    // staging decomposition: 2 cells of 8 floats per thread per chunk
    const int sb[2]  = { tid >> 3, (tid + 256) >> 3 };   // batch 0..63
    const int sk8 = tid & 7;                              // k8 within chunk

    const unsigned G0 = g_gen;   // generation base (monotone across replays)
    __syncthreads();

    for (int t = 0; t < Tq; t++) {
        const float* h_old = (t == 0) ? h0 : ((t & 1) ? g_hB : g_hA);
        float* h_new = (t & 1) ? g_hA : g_hB;

        float acc[3][4];
#pragma unroll
        for (int nt = 0; nt < 3; nt++)
#pragma unroll
            for (int e = 0; e < 4; e++) acc[nt][e] = 0.0f;

        float4 v[2][2];
        // prefetch + store chunk 0
#pragma unroll
        for (int i = 0; i < 2; i++) {
            const float* p = h_old + (size_t)sb[i] * Hq + sk8 * 8;
            v[i][0] = __ldcg((const float4*)p);
            v[i][1] = __ldcg((const float4*)(p + 4));
        }
#pragma unroll
        for (int i = 0; i < 2; i++) {
            uint2* dst = &Hs2[((size_t)(0 * 8 + sk8) * 64 + sb[i]) * 4];
            dst[0] = make_uint2(f2tf(v[i][0].x), f2tf(v[i][1].x));
            dst[1] = make_uint2(f2tf(v[i][0].y), f2tf(v[i][1].y));
            dst[2] = make_uint2(f2tf(v[i][0].z), f2tf(v[i][1].z));
            dst[3] = make_uint2(f2tf(v[i][0].w), f2tf(v[i][1].w));
        }
        __syncthreads();

        for (int c = 0; c < 16; c++) {
            const int cur = c & 1;
            if (c + 1 < 16) {
#pragma unroll
                for (int i = 0; i < 2; i++) {
                    const float* p = h_old + (size_t)sb[i] * Hq + (c + 1) * 64 + sk8 * 8;
                    v[i][0] = __ldcg((const float4*)p);
                    v[i][1] = __ldcg((const float4*)(p + 4));
                }
            }
            // compute 8 k8 on buffer cur
#pragma unroll
            for (int k8 = 0; k8 < 8; k8++) {
                const uint2* hb = Hs2 + (size_t)(cur * 8 + k8) * 64 * 4;
                const uint2 a02 = hb[(wm * 16 + g) * 4 + q];
                const uint2 a13 = hb[(wm * 16 + g + 8) * 4 + q];
                const uint2* wb = Ws2 + (size_t)(c * 8 + k8) * 48 * 4;
#pragma unroll
                for (int nt = 0; nt < 3; nt++) {
                    const uint2 bf = wb[(wn * 24 + nt * 8 + g) * 4 + q];
                    mma_tf32(acc[nt][0], acc[nt][1], acc[nt][2], acc[nt][3],
                             a02.x, a13.x, a02.y, a13.y, bf.x, bf.y);
                }
            }
            if (c + 1 < 16) {
                const int nb = (c + 1) & 1;
#pragma unroll
                for (int i = 0; i < 2; i++) {
                    uint2* dst = &Hs2[((size_t)(nb * 8 + sk8) * 64 + sb[i]) * 4];
                    dst[0] = make_uint2(f2tf(v[i][0].x), f2tf(v[i][1].x));
                    dst[1] = make_uint2(f2tf(v[i][0].y), f2tf(v[i][1].y));
                    dst[2] = make_uint2(f2tf(v[i][0].z), f2tf(v[i][1].z));
                    dst[3] = make_uint2(f2tf(v[i][0].w), f2tf(v[i][1].w));
                }
            }
            __syncthreads();
        }

        // ---- exchange fragments via smem (aliases h-buf0, safe: loop done) ----
#pragma unroll
        for (int nt = 0; nt < 3; nt++) {
            const int col = wn * 24 + nt * 8 + 2 * q;
            float2 o0, o1;
            o0.x = acc[nt][0]; o0.y = acc[nt][1];
            o1.x = acc[nt][2]; o1.y = acc[nt][3];
            *(float2*)&Cs[(wm * 16 + g) * 50 + col] = o0;
            *(float2*)&Cs[(wm * 16 + g + 8) * 50 + col] = o1;
        }
        __syncthreads();

        // ---- gate math: 4 outputs per thread ----
#pragma unroll
        for (int e = 0; e < 4; e++) {
            const int b = (tid >> 4) + e * 16;
            const int hc = hc0 + jj;
            const float rp = Cs[b * 50 + jj];
            const float zp = Cs[b * 50 + 16 + jj];
            const float np = Cs[b * 50 + 32 + jj];
            const float* xpb = xp + ((size_t)t * 64 + b) * Gq + hc;
            const float xr = xpb[0];
            const float xz = xpb[Hq];
            const float xn = xpb[2 * Hq];
            const float hp = __ldcg(h_old + (size_t)b * Hq + hc);
            const float r = 1.0f / (1.0f + __expf(-(xr + rp + bhr)));
            const float z = 1.0f / (1.0f + __expf(-(xz + zp + bhz)));
            const float nn = tanhf(xn + r * (np + bhn));
            const float hv = (1.0f - z) * nn + z * hp;
            h_new[(size_t)b * Hq + hc] = hv;
            hs[((size_t)b * Tq + t) * Hq + hc] = hv;
        }

        // ---- flag-array grid barrier (generation stamped) ----
        const unsigned stamp = G0 + (unsigned)t + 1u;
        __threadfence();
        __syncthreads();
        if (tid == 0) g_flag[blockIdx.x * 32] = stamp;
        if (blockIdx.x == 0) {
            if (tid < NB2) {
                while (g_flag[tid * 32] != stamp) { }
            }
            __syncthreads();
            if (tid == 0) g_gen = stamp;
        } else {
            if (tid == 0) {
                while (g_gen != stamp) { }
            }
            __syncthreads();
        }
        __threadfence();
    }
}

// Copy final hidden state hs[:, T-1, :] into the tail of d_out.
__global__ void copy_hlast_kernel(const float* __restrict__ hs, float* __restrict__ out)
{
    const int idx = blockIdx.x * 256 + threadIdx.x;
    if (idx < Bq * Hq) {
        const int b = idx >> 10;
        const int h = idx & 1023;
        out[idx] = hs[((size_t)b * Tq + (Tq - 1)) * Hq + h];
    }
}

// ============================================================================
extern "C" void kernel_launch(void* const* d_in, const int* in_sizes, int n_in,
                              void* d_out, int out_size)
{
    const float* inputs = (const float*)d_in[0];
    const float* h0     = (const float*)d_in[1];
    const float* w_ih   = (const float*)d_in[2];
    const float* w_hh   = (const float*)d_in[3];
    const float* b_ih   = (const float*)d_in[4];
    const float* b_hh   = (const float*)d_in[5];
    const float* w_out  = (const float*)d_in[6];
    const float* b_out  = (const float*)d_in[7];
    float* out = (float*)d_out;

    float *xp, *hs;
    cudaGetSymbolAddress((void**)&xp, g_xp);
    cudaGetSymbolAddress((void**)&hs, g_hs);

    // K1: x_proj = inputs @ w_ih^T + b_ih  -> xp[t][b][3H]
    {
        dim3 grid(Gq / 64, (Tq * Bq) / 128);
        mma_gemm<1><<<grid, 256>>>(inputs, w_ih, b_ih, xp, Gq, Iq);
    }

    // K2: persistent GRU recurrence -> hs[b][t][H]
    cudaFuncSetAttribute(gru_rec_mma, cudaFuncAttributeMaxDynamicSharedMemorySize, K2_SMEM);
    gru_rec_mma<<<NB2, 256, K2_SMEM>>>(xp, h0, w_hh, b_hh, hs);

    // K3: out = hs @ w_out^T + b_out -> d_out[0 : B*T*O]
    {
        dim3 grid(Oq / 64, (Bq * Tq) / 128);
        mma_gemm<0><<<grid, 256>>>(hs, w_out, b_out, out, Oq, Hq);
    }

    // K4: h_last tail
    copy_hlast_kernel<<<(Bq * Hq) / 256, 256>>>(hs, out + (size_t)Bq * Tq * Oq);
}

// round 4
// speedup vs baseline: 1.5763x; 1.5112x over previous
#include <cuda_runtime.h>
#include <math.h>

#define Bq 64
#define Tq 512
#define Iq 512
#define Hq 1024
#define Oq 512
#define Gq 3072

// -------- scratch (device globals: allocation-free rule) --------
__device__ float g_xp[(size_t)Tq * Bq * Gq];   // [t][b][3H]
__device__ float g_hs[(size_t)Bq * Tq * Hq];   // [b][t][H]
__device__ float g_h[2][Bq * Hq];              // h(t) ring, buf t&1
__device__ volatile unsigned g_flagv[64];      // per-block step stamps
__device__ volatile unsigned g_gen = 0;        // stamp base across replays

// -------- tf32 helpers --------
__device__ __forceinline__ unsigned f2tf(float f) {
    unsigned u; asm("cvt.rna.tf32.f32 %0, %1;" : "=r"(u) : "f"(f)); return u;
}
__device__ __forceinline__ void mma_tf32(
    float& d0, float& d1, float& d2, float& d3,
    unsigned a0, unsigned a1, unsigned a2, unsigned a3,
    unsigned b0, unsigned b1)
{
    asm volatile(
        "mma.sync.aligned.m16n8k8.row.col.f32.tf32.tf32.f32 "
        "{%0,%1,%2,%3},{%4,%5,%6,%7},{%8,%9},{%0,%1,%2,%3};"
        : "+f"(d0), "+f"(d1), "+f"(d2), "+f"(d3)
        : "r"(a0), "r"(a1), "r"(a2), "r"(a3), "r"(b0), "r"(b1));
}

__global__ void noop_kernel() {}

// ============================================================================
// MMA GEMM: C[m][n] = sum_k A[m][k] * Bw[n][k] + bias[n]
// Block tile 128(M) x 64(N), k-tile 32, 256 threads.
// SMEM planes padded by 1 uint2 -> conflict-free STS *and* LDS.
// MODE 1: A row m -> inputs[b=m&63][t=m>>6][:]   (x_proj GEMM)
// MODE 0: A row m at A + m*K                     (output GEMM)
// ============================================================================
#define APITCH 513   // 128*4 + 1 uint2 per k8 plane
#define BPITCH 257   // 64*4 + 1

template <int MODE>
__global__ __launch_bounds__(256) void mma_gemm(
    const float* __restrict__ A, const float* __restrict__ Bw,
    const float* __restrict__ bias, float* __restrict__ C,
    int N, int K)
{
    __shared__ __align__(16) uint2 As2[4 * APITCH];
    __shared__ __align__(16) uint2 Bs2[4 * BPITCH];

    const int tid = threadIdx.x;
    const int m0 = blockIdx.y * 128, n0 = blockIdx.x * 64;
    const int lane = tid & 31, warp = tid >> 5;
    const int g = lane >> 2, q = lane & 3;
    const int wm = warp >> 1, wn = warp & 1;

    const int ak8 = tid & 3;
    int am[2]; am[0] = tid >> 2; am[1] = (tid >> 2) + 64;
    size_t arow[2];
#pragma unroll
    for (int i = 0; i < 2; i++) {
        const int m = m0 + am[i];
        arow[i] = (MODE == 1) ? ((size_t)(m & 63) * Tq + (size_t)(m >> 6)) * Iq
                              : (size_t)m * (size_t)K;
    }
    const int bn = tid >> 2;
    const size_t brow = (size_t)(n0 + bn) * (size_t)K;

    float acc[2][4][4];
#pragma unroll
    for (int mt = 0; mt < 2; mt++)
#pragma unroll
        for (int nt = 0; nt < 4; nt++)
#pragma unroll
            for (int e = 0; e < 4; e++) acc[mt][nt][e] = 0.0f;

    float4 pa[2][2], pb[2];
#pragma unroll
    for (int i = 0; i < 2; i++) {
        pa[i][0] = __ldg((const float4*)(A + arow[i] + ak8 * 8));
        pa[i][1] = __ldg((const float4*)(A + arow[i] + ak8 * 8 + 4));
    }
    pb[0] = __ldg((const float4*)(Bw + brow + ak8 * 8));
    pb[1] = __ldg((const float4*)(Bw + brow + ak8 * 8 + 4));

    for (int k0 = 0; k0 < K; k0 += 32) {
#pragma unroll
        for (int i = 0; i < 2; i++) {
            uint2* dst = &As2[ak8 * APITCH + am[i] * 4];
            dst[0] = make_uint2(f2tf(pa[i][0].x), f2tf(pa[i][1].x));
            dst[1] = make_uint2(f2tf(pa[i][0].y), f2tf(pa[i][1].y));
            dst[2] = make_uint2(f2tf(pa[i][0].z), f2tf(pa[i][1].z));
            dst[3] = make_uint2(f2tf(pa[i][0].w), f2tf(pa[i][1].w));
        }
        {
            uint2* dst = &Bs2[ak8 * BPITCH + bn * 4];
            dst[0] = make_uint2(f2tf(pb[0].x), f2tf(pb[1].x));
            dst[1] = make_uint2(f2tf(pb[0].y), f2tf(pb[1].y));
            dst[2] = make_uint2(f2tf(pb[0].z), f2tf(pb[1].z));
            dst[3] = make_uint2(f2tf(pb[0].w), f2tf(pb[1].w));
        }
        __syncthreads();

        if (k0 + 32 < K) {
#pragma unroll
            for (int i = 0; i < 2; i++) {
                pa[i][0] = __ldg((const float4*)(A + arow[i] + k0 + 32 + ak8 * 8));
                pa[i][1] = __ldg((const float4*)(A + arow[i] + k0 + 32 + ak8 * 8 + 4));
            }
            pb[0] = __ldg((const float4*)(Bw + brow + k0 + 32 + ak8 * 8));
            pb[1] = __ldg((const float4*)(Bw + brow + k0 + 32 + ak8 * 8 + 4));
        }

#pragma unroll
        for (int k8 = 0; k8 < 4; k8++) {
            uint2 a02[2], a13[2];
#pragma unroll
            for (int mt = 0; mt < 2; mt++) {
                a02[mt] = As2[k8 * APITCH + (wm * 32 + mt * 16 + g) * 4 + q];
                a13[mt] = As2[k8 * APITCH + (wm * 32 + mt * 16 + g + 8) * 4 + q];
            }
            uint2 bf[4];
#pragma unroll
            for (int nt = 0; nt < 4; nt++)
                bf[nt] = Bs2[k8 * BPITCH + (wn * 32 + nt * 8 + g) * 4 + q];
#pragma unroll
            for (int mt = 0; mt < 2; mt++)
#pragma unroll
                for (int nt = 0; nt < 4; nt++)
                    mma_tf32(acc[mt][nt][0], acc[mt][nt][1], acc[mt][nt][2], acc[mt][nt][3],
                             a02[mt].x, a13[mt].x, a02[mt].y, a13[mt].y,
                             bf[nt].x, bf[nt].y);
        }
        __syncthreads();
    }

#pragma unroll
    for (int mt = 0; mt < 2; mt++) {
        const int mrow = m0 + wm * 32 + mt * 16 + g;
#pragma unroll
        for (int nt = 0; nt < 4; nt++) {
            const int col = n0 + wn * 32 + nt * 8 + 2 * q;
            const float2 bb = *(const float2*)&bias[col];
            float2 o0, o1;
            o0.x = acc[mt][nt][0] + bb.x; o0.y = acc[mt][nt][1] + bb.y;
            o1.x = acc[mt][nt][2] + bb.x; o1.y = acc[mt][nt][3] + bb.y;
            *(float2*)&C[(size_t)mrow * N + col] = o0;
            *(float2*)&C[(size_t)(mrow + 8) * N + col] = o1;
        }
    }
}

// ============================================================================
// Persistent GRU recurrence (tensor core) with one-sided flag barrier.
// 64 blocks x 256 threads, block owns 16 h-cols x 3 gates (n=48), m=64, k=1024.
// Weights resident in SMEM (tf32 pairs, 192KB); h streamed in 16 chunks of 64k,
// double-buffered with CONFLICT-FREE padded staging (pitch 257).
// ============================================================================
#define NB2 64
#define HPITCH 257                       // 64*4 + 1 uint2 per k8 plane
#define WS2_U2 (128 * 192)               // [k8 global][n=48][q=4]
#define HS2_U2 (16 * HPITCH)             // [buf*8 + k8][b][q] padded
#define K2_SMEM ((WS2_U2 + HS2_U2) * 8)  // 229504 B

__global__ __launch_bounds__(256, 1) void gru_rec_mma(
    const float* __restrict__ xp, const float* __restrict__ h0,
    const float* __restrict__ w_hh, const float* __restrict__ b_hh,
    float* __restrict__ hs)
{
    extern __shared__ uint2 sm2[];
    uint2* Ws2 = sm2;                    // weights, resident
    uint2* Hs2 = sm2 + WS2_U2;           // h staging, 2 x 8 padded planes
    float* Cs  = (float*)(sm2 + WS2_U2); // aliases buf0 post-loop [64][50]

    const int tid = threadIdx.x;
    const int lane = tid & 31, warp = tid >> 5;
    const int g = lane >> 2, q = lane & 3;
    const int wm = warp >> 1, wn = warp & 1;
    const int hc0 = blockIdx.x * 16;

    // ---- preload resident weights (once) ----
    for (int idx = tid; idx < 128 * 192; idx += 256) {
        const int k8 = idx / 192;
        const int r = idx - k8 * 192;
        const int n = r >> 2, qq = r & 3;
        const float* src = w_hh + ((size_t)(n >> 4) * Hq + hc0 + (n & 15)) * Hq + k8 * 8 + qq;
        Ws2[idx] = make_uint2(f2tf(src[0]), f2tf(src[4]));
    }
    const int jj = tid & 15;
    const int hc = hc0 + jj;
    const int bb0 = tid >> 4;  // gate-math base batch
    const float bhr = b_hh[hc];
    const float bhz = b_hh[Hq + hc];
    const float bhn = b_hh[2 * Hq + hc];

    // h_prev for own (b,hc) pairs lives in registers across steps
    float h_prev[4];
#pragma unroll
    for (int e = 0; e < 4; e++)
        h_prev[e] = h0[(size_t)(bb0 + e * 16) * Hq + hc];

    const int sb0 = tid >> 3;        // staging batch (and +32)
    const int sk8 = tid & 7;         // staging k8 within chunk

    const unsigned G0 = g_gen;
    __syncthreads();

    for (int t = 0; t < Tq; t++) {
        const float* h_old = (t == 0) ? h0 : g_h[(t - 1) & 1];
        float* h_new = g_h[t & 1];

        // xp prefetch for this step (in flight across poll + GEMM)
        float px[4][3];
        {
            const float* xpt = xp + (size_t)t * (Bq * Gq);
#pragma unroll
            for (int e = 0; e < 4; e++) {
                const float* p = xpt + (size_t)(bb0 + e * 16) * Gq + hc;
                px[e][0] = __ldcg(p);
                px[e][1] = __ldcg(p + Hq);
                px[e][2] = __ldcg(p + 2 * Hq);
            }
        }

        // ---- one-sided barrier: wait until every block published h(t-1) ----
        if (t > 0) {
            const unsigned need = G0 + (unsigned)t;
            if (tid < NB2) {
                while (g_flagv[tid] < need) { }
            }
            __syncthreads();
        }

        float acc[3][4];
#pragma unroll
        for (int nt = 0; nt < 3; nt++)
#pragma unroll
            for (int e = 0; e < 4; e++) acc[nt][e] = 0.0f;

        float4 v[2][2];
#pragma unroll
        for (int i = 0; i < 2; i++) {
            const float* p = h_old + (size_t)(sb0 + i * 32) * Hq + sk8 * 8;
            v[i][0] = __ldcg((const float4*)p);
            v[i][1] = __ldcg((const float4*)(p + 4));
        }
#pragma unroll
        for (int i = 0; i < 2; i++) {
            uint2* dst = &Hs2[(size_t)sk8 * HPITCH + (sb0 + i * 32) * 4];
            dst[0] = make_uint2(f2tf(v[i][0].x), f2tf(v[i][1].x));
            dst[1] = make_uint2(f2tf(v[i][0].y), f2tf(v[i][1].y));
            dst[2] = make_uint2(f2tf(v[i][0].z), f2tf(v[i][1].z));
            dst[3] = make_uint2(f2tf(v[i][0].w), f2tf(v[i][1].w));
        }
        __syncthreads();

        for (int c = 0; c < 16; c++) {
            const int cur = c & 1;
            if (c + 1 < 16) {
#pragma unroll
                for (int i = 0; i < 2; i++) {
                    const float* p = h_old + (size_t)(sb0 + i * 32) * Hq + (c + 1) * 64 + sk8 * 8;
                    v[i][0] = __ldcg((const float4*)p);
                    v[i][1] = __ldcg((const float4*)(p + 4));
                }
            }
#pragma unroll
            for (int k8 = 0; k8 < 8; k8++) {
                const uint2* hb = Hs2 + (size_t)(cur * 8 + k8) * HPITCH;
                const uint2 a02 = hb[(wm * 16 + g) * 4 + q];
                const uint2 a13 = hb[(wm * 16 + g + 8) * 4 + q];
                const uint2* wb = Ws2 + (size_t)(c * 8 + k8) * 192;
#pragma unroll
                for (int nt = 0; nt < 3; nt++) {
                    const uint2 bf = wb[(wn * 24 + nt * 8 + g) * 4 + q];
                    mma_tf32(acc[nt][0], acc[nt][1], acc[nt][2], acc[nt][3],
                             a02.x, a13.x, a02.y, a13.y, bf.x, bf.y);
                }
            }
            if (c + 1 < 16) {
                const int nb = (c + 1) & 1;
#pragma unroll
                for (int i = 0; i < 2; i++) {
                    uint2* dst = &Hs2[(size_t)(nb * 8 + sk8) * HPITCH + (sb0 + i * 32) * 4];
                    dst[0] = make_uint2(f2tf(v[i][0].x), f2tf(v[i][1].x));
                    dst[1] = make_uint2(f2tf(v[i][0].y), f2tf(v[i][1].y));
                    dst[2] = make_uint2(f2tf(v[i][0].z), f2tf(v[i][1].z));
                    dst[3] = make_uint2(f2tf(v[i][0].w), f2tf(v[i][1].w));
                }
            }
            __syncthreads();
        }

        // ---- exchange fragments via smem (aliases buf0; loop is done) ----
#pragma unroll
        for (int nt = 0; nt < 3; nt++) {
            const int col = wn * 24 + nt * 8 + 2 * q;
            float2 o0, o1;
            o0.x = acc[nt][0]; o0.y = acc[nt][1];
            o1.x = acc[nt][2]; o1.y = acc[nt][3];
            *(float2*)&Cs[(wm * 16 + g) * 50 + col] = o0;
            *(float2*)&Cs[(wm * 16 + g + 8) * 50 + col] = o1;
        }
        __syncthreads();

        // ---- gate math ----
#pragma unroll
        for (int e = 0; e < 4; e++) {
            const int b = bb0 + e * 16;
            const float rp = Cs[b * 50 + jj];
            const float zp = Cs[b * 50 + 16 + jj];
            const float np = Cs[b * 50 + 32 + jj];
            const float r = 1.0f / (1.0f + __expf(-(px[e][0] + rp + bhr)));
            const float z = 1.0f / (1.0f + __expf(-(px[e][1] + zp + bhz)));
            const float nn = tanhf(px[e][2] + r * (np + bhn));
            const float hv = (1.0f - z) * nn + z * h_prev[e];
            h_prev[e] = hv;
            h_new[(size_t)b * Hq + hc] = hv;
            hs[((size_t)b * Tq + t) * Hq + hc] = hv;
        }

        // ---- publish ----
        __threadfence();
        __syncthreads();
        if (tid == 0) g_flagv[blockIdx.x] = G0 + (unsigned)t + 1u;
    }

    if (blockIdx.x == 0 && tid == 0) g_gen = G0 + (unsigned)Tq;
}

// Copy final hidden state hs[:, T-1, :] into the tail of d_out.
__global__ void copy_hlast_kernel(const float* __restrict__ hs, float* __restrict__ out)
{
    const int idx = blockIdx.x * 256 + threadIdx.x;
    if (idx < Bq * Hq) {
        const int b = idx >> 10;
        const int h = idx & 1023;
        out[idx] = hs[((size_t)b * Tq + (Tq - 1)) * Hq + h];
    }
}

// ============================================================================
extern "C" void kernel_launch(void* const* d_in, const int* in_sizes, int n_in,
                              void* d_out, int out_size)
{
    const float* inputs = (const float*)d_in[0];
    const float* h0     = (const float*)d_in[1];
    const float* w_ih   = (const float*)d_in[2];
    const float* w_hh   = (const float*)d_in[3];
    const float* b_ih   = (const float*)d_in[4];
    const float* b_hh   = (const float*)d_in[5];
    const float* w_out  = (const float*)d_in[6];
    const float* b_out  = (const float*)d_in[7];
    float* out = (float*)d_out;

    float *xp, *hs;
    cudaGetSymbolAddress((void**)&xp, g_xp);
    cudaGetSymbolAddress((void**)&hs, g_hs);

    // two no-ops: aligns ncu's skip-5 capture onto gru_rec_mma
    noop_kernel<<<1, 32>>>();
    noop_kernel<<<1, 32>>>();

    // K1: x_proj = inputs @ w_ih^T + b_ih  -> xp[t][b][3H]
    {
        dim3 grid(Gq / 64, (Tq * Bq) / 128);
        mma_gemm<1><<<grid, 256>>>(inputs, w_ih, b_ih, xp, Gq, Iq);
    }

    // K2: persistent GRU recurrence -> hs[b][t][H]
    cudaFuncSetAttribute(gru_rec_mma, cudaFuncAttributeMaxDynamicSharedMemorySize, K2_SMEM);
    gru_rec_mma<<<NB2, 256, K2_SMEM>>>(xp, h0, w_hh, b_hh, hs);

    // K3: out = hs @ w_out^T + b_out -> d_out[0 : B*T*O]
    {
        dim3 grid(Oq / 64, (Bq * Tq) / 128);
        mma_gemm<0><<<grid, 256>>>(hs, w_out, b_out, out, Oq, Hq);
    }

    // K4: h_last tail
    copy_hlast_kernel<<<(Bq * Hq) / 256, 256>>>(hs, out + (size_t)Bq * Tq * Oq);
}

// round 5
// speedup vs baseline: 1.6385x; 1.0395x over previous
#include <cuda_runtime.h>
#include <math.h>

#define Bq 64
#define Tq 512
#define Iq 512
#define Hq 1024
#define Oq 512
#define Gq 3072

// -------- scratch (device globals: allocation-free rule) --------
__device__ float g_xp[(size_t)Tq * Bq * Gq];   // [t][b][3H]
__device__ float g_hs[(size_t)Bq * Tq * Hq];   // [b][t][H]
__device__ float g_h[2][Bq * Hq];              // h(t) ring, buf t&1
__device__ volatile unsigned g_flagv[64];      // per-block step stamps
__device__ volatile unsigned g_gen = 0;        // stamp base across replays

// -------- tf32 helpers --------
__device__ __forceinline__ unsigned f2tf(float f) {
    unsigned u; asm("cvt.rna.tf32.f32 %0, %1;" : "=r"(u) : "f"(f)); return u;
}
__device__ __forceinline__ void mma_tf32(
    float& d0, float& d1, float& d2, float& d3,
    unsigned a0, unsigned a1, unsigned a2, unsigned a3,
    unsigned b0, unsigned b1)
{
    asm volatile(
        "mma.sync.aligned.m16n8k8.row.col.f32.tf32.tf32.f32 "
        "{%0,%1,%2,%3},{%4,%5,%6,%7},{%8,%9},{%0,%1,%2,%3};"
        : "+f"(d0), "+f"(d1), "+f"(d2), "+f"(d3)
        : "r"(a0), "r"(a1), "r"(a2), "r"(a3), "r"(b0), "r"(b1));
}

__global__ void noop_kernel() {}

// ============================================================================
// MMA GEMM: C[m][n] = sum_k A[m][k] * Bw[n][k] + bias[n]
// Block tile 128(M) x 64(N), k-tile 32, 256 threads.
// SMEM planes padded by 1 uint2 -> conflict-free STS *and* LDS.
// MODE 1: A row m -> inputs[b=m&63][t=m>>6][:]   (x_proj GEMM)
// MODE 0: A row m at A + m*K                     (output GEMM)
// ============================================================================
#define APITCH 513   // 128*4 + 1 uint2 per k8 plane
#define BPITCH 257   // 64*4 + 1

template <int MODE>
__global__ __launch_bounds__(256) void mma_gemm(
    const float* __restrict__ A, const float* __restrict__ Bw,
    const float* __restrict__ bias, float* __restrict__ C,
    int N, int K)
{
    __shared__ __align__(16) uint2 As2[4 * APITCH];
    __shared__ __align__(16) uint2 Bs2[4 * BPITCH];

    const int tid = threadIdx.x;
    const int m0 = blockIdx.y * 128, n0 = blockIdx.x * 64;
    const int lane = tid & 31, warp = tid >> 5;
    const int g = lane >> 2, q = lane & 3;
    const int wm = warp >> 1, wn = warp & 1;

    const int ak8 = tid & 3;
    int am[2]; am[0] = tid >> 2; am[1] = (tid >> 2) + 64;
    size_t arow[2];
#pragma unroll
    for (int i = 0; i < 2; i++) {
        const int m = m0 + am[i];
        arow[i] = (MODE == 1) ? ((size_t)(m & 63) * Tq + (size_t)(m >> 6)) * Iq
                              : (size_t)m * (size_t)K;
    }
    const int bn = tid >> 2;
    const size_t brow = (size_t)(n0 + bn) * (size_t)K;

    float acc[2][4][4];
#pragma unroll
    for (int mt = 0; mt < 2; mt++)
#pragma unroll
        for (int nt = 0; nt < 4; nt++)
#pragma unroll
            for (int e = 0; e < 4; e++) acc[mt][nt][e] = 0.0f;

    float4 pa[2][2], pb[2];
#pragma unroll
    for (int i = 0; i < 2; i++) {
        pa[i][0] = __ldg((const float4*)(A + arow[i] + ak8 * 8));
        pa[i][1] = __ldg((const float4*)(A + arow[i] + ak8 * 8 + 4));
    }
    pb[0] = __ldg((const float4*)(Bw + brow + ak8 * 8));
    pb[1] = __ldg((const float4*)(Bw + brow + ak8 * 8 + 4));

    for (int k0 = 0; k0 < K; k0 += 32) {
#pragma unroll
        for (int i = 0; i < 2; i++) {
            uint2* dst = &As2[ak8 * APITCH + am[i] * 4];
            dst[0] = make_uint2(f2tf(pa[i][0].x), f2tf(pa[i][1].x));
            dst[1] = make_uint2(f2tf(pa[i][0].y), f2tf(pa[i][1].y));
            dst[2] = make_uint2(f2tf(pa[i][0].z), f2tf(pa[i][1].z));
            dst[3] = make_uint2(f2tf(pa[i][0].w), f2tf(pa[i][1].w));
        }
        {
            uint2* dst = &Bs2[ak8 * BPITCH + bn * 4];
            dst[0] = make_uint2(f2tf(pb[0].x), f2tf(pb[1].x));
            dst[1] = make_uint2(f2tf(pb[0].y), f2tf(pb[1].y));
            dst[2] = make_uint2(f2tf(pb[0].z), f2tf(pb[1].z));
            dst[3] = make_uint2(f2tf(pb[0].w), f2tf(pb[1].w));
        }
        __syncthreads();

        if (k0 + 32 < K) {
#pragma unroll
            for (int i = 0; i < 2; i++) {
                pa[i][0] = __ldg((const float4*)(A + arow[i] + k0 + 32 + ak8 * 8));
                pa[i][1] = __ldg((const float4*)(A + arow[i] + k0 + 32 + ak8 * 8 + 4));
            }
            pb[0] = __ldg((const float4*)(Bw + brow + k0 + 32 + ak8 * 8));
            pb[1] = __ldg((const float4*)(Bw + brow + k0 + 32 + ak8 * 8 + 4));
        }

#pragma unroll
        for (int k8 = 0; k8 < 4; k8++) {
            uint2 a02[2], a13[2];
#pragma unroll
            for (int mt = 0; mt < 2; mt++) {
                a02[mt] = As2[k8 * APITCH + (wm * 32 + mt * 16 + g) * 4 + q];
                a13[mt] = As2[k8 * APITCH + (wm * 32 + mt * 16 + g + 8) * 4 + q];
            }
            uint2 bf[4];
#pragma unroll
            for (int nt = 0; nt < 4; nt++)
                bf[nt] = Bs2[k8 * BPITCH + (wn * 32 + nt * 8 + g) * 4 + q];
#pragma unroll
            for (int mt = 0; mt < 2; mt++)
#pragma unroll
                for (int nt = 0; nt < 4; nt++)
                    mma_tf32(acc[mt][nt][0], acc[mt][nt][1], acc[mt][nt][2], acc[mt][nt][3],
                             a02[mt].x, a13[mt].x, a02[mt].y, a13[mt].y,
                             bf[nt].x, bf[nt].y);
        }
        __syncthreads();
    }

#pragma unroll
    for (int mt = 0; mt < 2; mt++) {
        const int mrow = m0 + wm * 32 + mt * 16 + g;
#pragma unroll
        for (int nt = 0; nt < 4; nt++) {
            const int col = n0 + wn * 32 + nt * 8 + 2 * q;
            const float2 bb = *(const float2*)&bias[col];
            float2 o0, o1;
            o0.x = acc[mt][nt][0] + bb.x; o0.y = acc[mt][nt][1] + bb.y;
            o1.x = acc[mt][nt][2] + bb.x; o1.y = acc[mt][nt][3] + bb.y;
            *(float2*)&C[(size_t)mrow * N + col] = o0;
            *(float2*)&C[(size_t)(mrow + 8) * N + col] = o1;
        }
    }
}

// ============================================================================
// Persistent GRU recurrence (tensor core) with one-sided flag barrier.
// 64 blocks x 256 threads, block owns 16 h-cols x 3 gates (n=48), m=64, k=1024.
// Weights resident in SMEM (tf32 pairs, 192KB); h streamed in 16 chunks of 64k,
// double-buffered with CONFLICT-FREE padded staging (pitch 257).
// ============================================================================
#define NB2 64
#define HPITCH 257                       // 64*4 + 1 uint2 per k8 plane
#define WS2_U2 (128 * 192)               // [k8 global][n=48][q=4]
#define HS2_U2 (16 * HPITCH)             // [buf*8 + k8][b][q] padded
#define K2_SMEM ((WS2_U2 + HS2_U2) * 8)  // 229504 B

__global__ __launch_bounds__(256, 1) void gru_rec_mma(
    const float* __restrict__ xp, const float* __restrict__ h0,
    const float* __restrict__ w_hh, const float* __restrict__ b_hh,
    float* __restrict__ hs)
{
    extern __shared__ uint2 sm2[];
    uint2* Ws2 = sm2;                    // weights, resident
    uint2* Hs2 = sm2 + WS2_U2;           // h staging, 2 x 8 padded planes
    float* Cs  = (float*)(sm2 + WS2_U2); // aliases buf0 post-loop [64][50]

    const int tid = threadIdx.x;
    const int lane = tid & 31, warp = tid >> 5;
    const int g = lane >> 2, q = lane & 3;
    const int wm = warp >> 1, wn = warp & 1;
    const int hc0 = blockIdx.x * 16;

    // ---- preload resident weights (once) ----
    for (int idx = tid; idx < 128 * 192; idx += 256) {
        const int k8 = idx / 192;
        const int r = idx - k8 * 192;
        const int n = r >> 2, qq = r & 3;
        const float* src = w_hh + ((size_t)(n >> 4) * Hq + hc0 + (n & 15)) * Hq + k8 * 8 + qq;
        Ws2[idx] = make_uint2(f2tf(src[0]), f2tf(src[4]));
    }
    const int jj = tid & 15;
    const int hc = hc0 + jj;
    const int bb0 = tid >> 4;  // gate-math base batch
    const float bhr = b_hh[hc];
    const float bhz = b_hh[Hq + hc];
    const float bhn = b_hh[2 * Hq + hc];

    // h_prev for own (b,hc) pairs lives in registers across steps
    float h_prev[4];
#pragma unroll
    for (int e = 0; e < 4; e++)
        h_prev[e] = h0[(size_t)(bb0 + e * 16) * Hq + hc];

    const int sb0 = tid >> 3;        // staging batch (and +32)
    const int sk8 = tid & 7;         // staging k8 within chunk

    const unsigned G0 = g_gen;
    __syncthreads();

    for (int t = 0; t < Tq; t++) {
        const float* h_old = (t == 0) ? h0 : g_h[(t - 1) & 1];
        float* h_new = g_h[t & 1];

        // xp prefetch for this step (in flight across poll + GEMM)
        float px[4][3];
        {
            const float* xpt = xp + (size_t)t * (Bq * Gq);
#pragma unroll
            for (int e = 0; e < 4; e++) {
                const float* p = xpt + (size_t)(bb0 + e * 16) * Gq + hc;
                px[e][0] = __ldcg(p);
                px[e][1] = __ldcg(p + Hq);
                px[e][2] = __ldcg(p + 2 * Hq);
            }
        }

        // ---- one-sided barrier: wait until every block published h(t-1) ----
        if (t > 0) {
            const unsigned need = G0 + (unsigned)t;
            if (tid < NB2) {
                while (g_flagv[tid] < need) { }
            }
            __syncthreads();
        }

        float acc[3][4];
#pragma unroll
        for (int nt = 0; nt < 3; nt++)
#pragma unroll
            for (int e = 0; e < 4; e++) acc[nt][e] = 0.0f;

        float4 v[2][2];
#pragma unroll
        for (int i = 0; i < 2; i++) {
            const float* p = h_old + (size_t)(sb0 + i * 32) * Hq + sk8 * 8;
            v[i][0] = __ldcg((const float4*)p);
            v[i][1] = __ldcg((const float4*)(p + 4));
        }
#pragma unroll
        for (int i = 0; i < 2; i++) {
            uint2* dst = &Hs2[(size_t)sk8 * HPITCH + (sb0 + i * 32) * 4];
            dst[0] = make_uint2(f2tf(v[i][0].x), f2tf(v[i][1].x));
            dst[1] = make_uint2(f2tf(v[i][0].y), f2tf(v[i][1].y));
            dst[2] = make_uint2(f2tf(v[i][0].z), f2tf(v[i][1].z));
            dst[3] = make_uint2(f2tf(v[i][0].w), f2tf(v[i][1].w));
        }
        __syncthreads();

        for (int c = 0; c < 16; c++) {
            const int cur = c & 1;
            if (c + 1 < 16) {
#pragma unroll
                for (int i = 0; i < 2; i++) {
                    const float* p = h_old + (size_t)(sb0 + i * 32) * Hq + (c + 1) * 64 + sk8 * 8;
                    v[i][0] = __ldcg((const float4*)p);
                    v[i][1] = __ldcg((const float4*)(p + 4));
                }
            }
#pragma unroll
            for (int k8 = 0; k8 < 8; k8++) {
                const uint2* hb = Hs2 + (size_t)(cur * 8 + k8) * HPITCH;
                const uint2 a02 = hb[(wm * 16 + g) * 4 + q];
                const uint2 a13 = hb[(wm * 16 + g + 8) * 4 + q];
                const uint2* wb = Ws2 + (size_t)(c * 8 + k8) * 192;
#pragma unroll
                for (int nt = 0; nt < 3; nt++) {
                    const uint2 bf = wb[(wn * 24 + nt * 8 + g) * 4 + q];
                    mma_tf32(acc[nt][0], acc[nt][1], acc[nt][2], acc[nt][3],
                             a02.x, a13.x, a02.y, a13.y, bf.x, bf.y);
                }
            }
            if (c + 1 < 16) {
                const int nb = (c + 1) & 1;
#pragma unroll
                for (int i = 0; i < 2; i++) {
                    uint2* dst = &Hs2[(size_t)(nb * 8 + sk8) * HPITCH + (sb0 + i * 32) * 4];
                    dst[0] = make_uint2(f2tf(v[i][0].x), f2tf(v[i][1].x));
                    dst[1] = make_uint2(f2tf(v[i][0].y), f2tf(v[i][1].y));
                    dst[2] = make_uint2(f2tf(v[i][0].z), f2tf(v[i][1].z));
                    dst[3] = make_uint2(f2tf(v[i][0].w), f2tf(v[i][1].w));
                }
            }
            __syncthreads();
        }

        // ---- exchange fragments via smem (aliases buf0; loop is done) ----
#pragma unroll
        for (int nt = 0; nt < 3; nt++) {
            const int col = wn * 24 + nt * 8 + 2 * q;
            float2 o0, o1;
            o0.x = acc[nt][0]; o0.y = acc[nt][1];
            o1.x = acc[nt][2]; o1.y = acc[nt][3];
            *(float2*)&Cs[(wm * 16 + g) * 50 + col] = o0;
            *(float2*)&Cs[(wm * 16 + g + 8) * 50 + col] = o1;
        }
        __syncthreads();

        // ---- gate math ----
#pragma unroll
        for (int e = 0; e < 4; e++) {
            const int b = bb0 + e * 16;
            const float rp = Cs[b * 50 + jj];
            const float zp = Cs[b * 50 + 16 + jj];
            const float np = Cs[b * 50 + 32 + jj];
            const float r = 1.0f / (1.0f + __expf(-(px[e][0] + rp + bhr)));
            const float z = 1.0f / (1.0f + __expf(-(px[e][1] + zp + bhz)));
            const float nn = tanhf(px[e][2] + r * (np + bhn));
            const float hv = (1.0f - z) * nn + z * h_prev[e];
            h_prev[e] = hv;
            h_new[(size_t)b * Hq + hc] = hv;
            hs[((size_t)b * Tq + t) * Hq + hc] = hv;
        }

        // ---- publish ----
        __threadfence();
        __syncthreads();
        if (tid == 0) g_flagv[blockIdx.x] = G0 + (unsigned)t + 1u;
    }

    if (blockIdx.x == 0 && tid == 0) g_gen = G0 + (unsigned)Tq;
}

// Copy final hidden state hs[:, T-1, :] into the tail of d_out.
__global__ void copy_hlast_kernel(const float* __restrict__ hs, float* __restrict__ out)
{
    const int idx = blockIdx.x * 256 + threadIdx.x;
    if (idx < Bq * Hq) {
        const int b = idx >> 10;
        const int h = idx & 1023;
        out[idx] = hs[((size_t)b * Tq + (Tq - 1)) * Hq + h];
    }
}

// ============================================================================
extern "C" void kernel_launch(void* const* d_in, const int* in_sizes, int n_in,
                              void* d_out, int out_size)
{
    const float* inputs = (const float*)d_in[0];
    const float* h0     = (const float*)d_in[1];
    const float* w_ih   = (const float*)d_in[2];
    const float* w_hh   = (const float*)d_in[3];
    const float* b_ih   = (const float*)d_in[4];
    const float* b_hh   = (const float*)d_in[5];
    const float* w_out  = (const float*)d_in[6];
    const float* b_out  = (const float*)d_in[7];
    float* out = (float*)d_out;

    float *xp, *hs;
    cudaGetSymbolAddress((void**)&xp, g_xp);
    cudaGetSymbolAddress((void**)&hs, g_hs);

    // two no-ops: aligns ncu's skip-5 capture onto gru_rec_mma
    noop_kernel<<<1, 32>>>();
    noop_kernel<<<1, 32>>>();

    // K1: x_proj = inputs @ w_ih^T + b_ih  -> xp[t][b][3H]
    {
        dim3 grid(Gq / 64, (Tq * Bq) / 128);
        mma_gemm<1><<<grid, 256>>>(inputs, w_ih, b_ih, xp, Gq, Iq);
    }

    // K2: persistent GRU recurrence -> hs[b][t][H]
    cudaFuncSetAttribute(gru_rec_mma, cudaFuncAttributeMaxDynamicSharedMemorySize, K2_SMEM);
    gru_rec_mma<<<NB2, 256, K2_SMEM>>>(xp, h0, w_hh, b_hh, hs);

    // K3: out = hs @ w_out^T + b_out -> d_out[0 : B*T*O]
    {
        dim3 grid(Oq / 64, (Bq * Tq) / 128);
        mma_gemm<0><<<grid, 256>>>(hs, w_out, b_out, out, Oq, Hq);
    }

    // K4: h_last tail
    copy_hlast_kernel<<<(Bq * Hq) / 256, 256>>>(hs, out + (size_t)Bq * Tq * Oq);
}

// round 6
// speedup vs baseline: 2.3513x; 1.4350x over previous
#include <cuda_runtime.h>
#include <cuda_fp16.h>
#include <math.h>

#define Bq 64
#define Tq 512
#define Iq 512
#define Hq 1024
#define Oq 512
#define Gq 3072

__device__ float  g_xp[(size_t)Tq * Bq * Gq];
__device__ __half g_hs16[(size_t)Bq * Tq * Hq];
__device__ __half g_h16[2][Bq * Hq];
__device__ volatile unsigned g_flagv[64];
__device__ volatile unsigned g_gen = 0;

__device__ __forceinline__ unsigned pk2(float a, float b) {
    __half2 h = __floats2half2_rn(a, b);
    return *reinterpret_cast<unsigned*>(&h);
}
__device__ __forceinline__ void mma_f16(
    float& d0, float& d1, float& d2, float& d3,
    unsigned a0, unsigned a1, unsigned a2, unsigned a3,
    unsigned b0, unsigned b1)
{
    asm volatile(
        "mma.sync.aligned.m16n8k16.row.col.f32.f16.f16.f32 "
        "{%0,%1,%2,%3},{%4,%5,%6,%7},{%8,%9},{%0,%1,%2,%3};"
        : "+f"(d0), "+f"(d1), "+f"(d2), "+f"(d3)
        : "r"(a0), "r"(a1), "r"(a2), "r"(a3), "r"(b0), "r"(b1));
}

__global__ void noop_kernel() {}

// ============================================================================
// fp16 MMA GEMM, block tile 128x64, k-tile 64, 256 threads.
// SMEM plane (k16): row -> 4 uint2, uint2 q = {pair(2q,2q+1), pair(2q+8,2q+9)}
// MODE 1: A fp32, row m -> inputs[b=m&63][t=m>>6][:]   (K1)
// MODE 0: A fp16 (g_hs16), row m at A16 + m*K           (K3)
// ============================================================================
#define APIT 513
#define BPIT 257

template <int MODE>
__global__ __launch_bounds__(256) void mma_gemm(
    const float* __restrict__ A, const __half* __restrict__ A16,
    const float* __restrict__ Bw, const float* __restrict__ bias,
    float* __restrict__ C, int N, int K)
{
    __shared__ __align__(16) uint2 As2[4 * APIT];
    __shared__ __align__(16) uint2 Bs2[4 * BPIT];

    const int tid = threadIdx.x;
    const int m0 = blockIdx.y * 128, n0 = blockIdx.x * 64;
    const int lane = tid & 31, warp = tid >> 5;
    const int g = lane >> 2, q = lane & 3;
    const int wm = warp >> 1, wn = warp & 1;

    const int ap = tid & 3;      // k16 plane
    const int ar = tid >> 2;     // row (and +64 for A)
    size_t arow[2];
#pragma unroll
    for (int i = 0; i < 2; i++) {
        const int m = m0 + ar + i * 64;
        arow[i] = (MODE == 1) ? ((size_t)(m & 63) * Tq + (size_t)(m >> 6)) * Iq
                              : (size_t)m * (size_t)K;
    }
    const size_t brow = (size_t)(n0 + ar) * (size_t)K;

    float acc[2][4][4];
#pragma unroll
    for (int mt = 0; mt < 2; mt++)
#pragma unroll
        for (int nt = 0; nt < 4; nt++)
#pragma unroll
            for (int e = 0; e < 4; e++) acc[mt][nt][e] = 0.0f;

    float4 pa[2][4], pb[4];
    uint4 ha[2][2];
#pragma unroll
    for (int i = 0; i < 2; i++) {
        if (MODE == 1) {
#pragma unroll
            for (int j = 0; j < 4; j++)
                pa[i][j] = __ldg((const float4*)(A + arow[i] + ap * 16 + j * 4));
        } else {
            ha[i][0] = __ldg((const uint4*)(A16 + arow[i] + ap * 16));
            ha[i][1] = __ldg((const uint4*)(A16 + arow[i] + ap * 16 + 8));
        }
    }
#pragma unroll
    for (int j = 0; j < 4; j++)
        pb[j] = __ldg((const float4*)(Bw + brow + ap * 16 + j * 4));

    for (int k0 = 0; k0 < K; k0 += 64) {
#pragma unroll
        for (int i = 0; i < 2; i++) {
            uint2* d = &As2[ap * APIT + (ar + i * 64) * 4];
            if (MODE == 1) {
                d[0] = make_uint2(pk2(pa[i][0].x, pa[i][0].y), pk2(pa[i][2].x, pa[i][2].y));
                d[1] = make_uint2(pk2(pa[i][0].z, pa[i][0].w), pk2(pa[i][2].z, pa[i][2].w));
                d[2] = make_uint2(pk2(pa[i][1].x, pa[i][1].y), pk2(pa[i][3].x, pa[i][3].y));
                d[3] = make_uint2(pk2(pa[i][1].z, pa[i][1].w), pk2(pa[i][3].z, pa[i][3].w));
            } else {
                d[0] = make_uint2(ha[i][0].x, ha[i][1].x);
                d[1] = make_uint2(ha[i][0].y, ha[i][1].y);
                d[2] = make_uint2(ha[i][0].z, ha[i][1].z);
                d[3] = make_uint2(ha[i][0].w, ha[i][1].w);
            }
        }
        {
            uint2* d = &Bs2[ap * BPIT + ar * 4];
            d[0] = make_uint2(pk2(pb[0].x, pb[0].y), pk2(pb[2].x, pb[2].y));
            d[1] = make_uint2(pk2(pb[0].z, pb[0].w), pk2(pb[2].z, pb[2].w));
            d[2] = make_uint2(pk2(pb[1].x, pb[1].y), pk2(pb[3].x, pb[3].y));
            d[3] = make_uint2(pk2(pb[1].z, pb[1].w), pk2(pb[3].z, pb[3].w));
        }
        __syncthreads();

        if (k0 + 64 < K) {
#pragma unroll
            for (int i = 0; i < 2; i++) {
                if (MODE == 1) {
#pragma unroll
                    for (int j = 0; j < 4; j++)
                        pa[i][j] = __ldg((const float4*)(A + arow[i] + k0 + 64 + ap * 16 + j * 4));
                } else {
                    ha[i][0] = __ldg((const uint4*)(A16 + arow[i] + k0 + 64 + ap * 16));
                    ha[i][1] = __ldg((const uint4*)(A16 + arow[i] + k0 + 64 + ap * 16 + 8));
                }
            }
#pragma unroll
            for (int j = 0; j < 4; j++)
                pb[j] = __ldg((const float4*)(Bw + brow + k0 + 64 + ap * 16 + j * 4));
        }

#pragma unroll
        for (int p = 0; p < 4; p++) {
            uint2 aLo[2], aHi[2];
#pragma unroll
            for (int mt = 0; mt < 2; mt++) {
                const int r = wm * 32 + mt * 16 + g;
                aLo[mt] = As2[p * APIT + r * 4 + q];
                aHi[mt] = As2[p * APIT + (r + 8) * 4 + q];
            }
#pragma unroll
            for (int nt = 0; nt < 4; nt++) {
                const uint2 bb = Bs2[p * BPIT + (wn * 32 + nt * 8 + g) * 4 + q];
#pragma unroll
                for (int mt = 0; mt < 2; mt++)
                    mma_f16(acc[mt][nt][0], acc[mt][nt][1], acc[mt][nt][2], acc[mt][nt][3],
                            aLo[mt].x, aHi[mt].x, aLo[mt].y, aHi[mt].y, bb.x, bb.y);
            }
        }
        __syncthreads();
    }

#pragma unroll
    for (int mt = 0; mt < 2; mt++) {
        const int mrow = m0 + wm * 32 + mt * 16 + g;
#pragma unroll
        for (int nt = 0; nt < 4; nt++) {
            const int col = n0 + wn * 32 + nt * 8 + 2 * q;
            const float2 bb = *(const float2*)&bias[col];
            float2 o0, o1;
            o0.x = acc[mt][nt][0] + bb.x; o0.y = acc[mt][nt][1] + bb.y;
            o1.x = acc[mt][nt][2] + bb.x; o1.y = acc[mt][nt][3] + bb.y;
            *(float2*)&C[(size_t)mrow * N + col] = o0;
            *(float2*)&C[(size_t)(mrow + 8) * N + col] = o1;
        }
    }
}

// ============================================================================
// Persistent GRU recurrence, fp16 MMA. 64 blocks x 256 threads.
// Block: n=48 (16 h-cols x 3 gates), m=64 batch, k=1024.
// Weights resident fp16 (96KB); FULL h staged per step (131.5KB), ONE sync.
// Warps: wk = warp>>1 (k-quarter of 256), wmg = warp&1 (m-half of 32).
// 4-way k-reduce via SMEM (aliases staging); wk==0 warps do gates in-register.
// ============================================================================
#define NB2 64
#define WPLANE 192                      // uint2 per weight k16 plane (48 rows x 4)
#define HPIT 257                        // uint2 per h k16 plane (64x4 + 1)
#define WS_U2 (64 * WPLANE)
#define HS_U2 (64 * HPIT)
#define K2_SMEM ((WS_U2 + HS_U2) * 8)   // 229888 B
#define REDP 56                         // reduce pitch (floats)

__global__ __launch_bounds__(256, 1) void gru_rec_mma(
    const float* __restrict__ xp, const float* __restrict__ h0,
    const float* __restrict__ w_hh, const float* __restrict__ b_hh,
    __half* __restrict__ hs16)
{
    extern __shared__ uint2 sm2[];
    uint2* Ws2 = sm2;
    uint2* Hs2 = sm2 + WS_U2;
    float* Redf = (float*)Hs2;          // aliases staging after GEMM

    const int tid = threadIdx.x;
    const int lane = tid & 31, warp = tid >> 5;
    const int g = lane >> 2, q = lane & 3;
    const int wk = warp >> 1, wmg = warp & 1;
    const int hc0 = blockIdx.x * 16;

    for (int idx = tid; idx < WS_U2; idx += 256) {
        const int k16 = idx / WPLANE;
        const int r = idx - k16 * WPLANE;
        const int n = r >> 2, qq = r & 3;
        const float* src = w_hh + ((size_t)(n >> 4) * Hq + hc0 + (n & 15)) * Hq + k16 * 16;
        Ws2[idx] = make_uint2(pk2(src[2 * qq], src[2 * qq + 1]),
                              pk2(src[2 * qq + 8], src[2 * qq + 9]));
    }

    float bhr[4], bhz[4], bhn[4], h_prev[16];
    if (wk == 0) {
#pragma unroll
        for (int ntp = 0; ntp < 2; ntp++)
#pragma unroll
            for (int e = 0; e < 2; e++) {
                const int cb = ntp * 2 + e;
                const int hc = hc0 + ntp * 8 + 2 * q + e;
                bhr[cb] = b_hh[hc];
                bhz[cb] = b_hh[Hq + hc];
                bhn[cb] = b_hh[2 * Hq + hc];
            }
#pragma unroll
        for (int mt = 0; mt < 2; mt++)
#pragma unroll
            for (int rr = 0; rr < 2; rr++)
#pragma unroll
                for (int ntp = 0; ntp < 2; ntp++)
#pragma unroll
                    for (int e = 0; e < 2; e++) {
                        const int u = mt * 8 + rr * 4 + ntp * 2 + e;
                        const int b = wmg * 32 + mt * 16 + g + 8 * rr;
                        const int hc = hc0 + ntp * 8 + 2 * q + e;
                        h_prev[u] = h0[(size_t)b * Hq + hc];
                    }
    }

    const int sb = tid >> 2;
    const int sk0 = tid & 3;

    const unsigned G0 = g_gen;
    __syncthreads();

    for (int t = 0; t < Tq; t++) {
        const __half* h16old = g_h16[(t - 1) & 1];
        __half* h16new = g_h16[t & 1];

        float px[16][3];
        if (wk == 0) {
            const float* xpt = xp + (size_t)t * (Bq * Gq);
#pragma unroll
            for (int mt = 0; mt < 2; mt++)
#pragma unroll
                for (int rr = 0; rr < 2; rr++)
#pragma unroll
                    for (int ntp = 0; ntp < 2; ntp++)
#pragma unroll
                        for (int e = 0; e < 2; e++) {
                            const int u = mt * 8 + rr * 4 + ntp * 2 + e;
                            const int b = wmg * 32 + mt * 16 + g + 8 * rr;
                            const int hc = hc0 + ntp * 8 + 2 * q + e;
                            const float* p = xpt + (size_t)b * Gq + hc;
                            px[u][0] = __ldg(p);
                            px[u][1] = __ldg(p + Hq);
                            px[u][2] = __ldg(p + 2 * Hq);
                        }
        }

        if (t > 0) {
            const unsigned need = G0 + (unsigned)t;
            if (tid < NB2) {
                while (g_flagv[tid] < need) { }
            }
            __syncthreads();
        }

        // ---- stage full h ----
        if (t == 0) {
#pragma unroll 4
            for (int i = 0; i < 16; i++) {
                const int k16 = sk0 + 4 * i;
                const float* p = h0 + (size_t)sb * Hq + k16 * 16;
                const float4 f0 = __ldg((const float4*)p);
                const float4 f1 = __ldg((const float4*)(p + 4));
                const float4 f2 = __ldg((const float4*)(p + 8));
                const float4 f3 = __ldg((const float4*)(p + 12));
                uint2* d = &Hs2[k16 * HPIT + sb * 4];
                d[0] = make_uint2(pk2(f0.x, f0.y), pk2(f2.x, f2.y));
                d[1] = make_uint2(pk2(f0.z, f0.w), pk2(f2.z, f2.w));
                d[2] = make_uint2(pk2(f1.x, f1.y), pk2(f3.x, f3.y));
                d[3] = make_uint2(pk2(f1.z, f1.w), pk2(f3.z, f3.w));
            }
        } else {
#pragma unroll 4
            for (int i = 0; i < 16; i++) {
                const int k16 = sk0 + 4 * i;
                const uint4* p = (const uint4*)(h16old + (size_t)sb * Hq + k16 * 16);
                const uint4 lo = __ldcg(p);
                const uint4 hi = __ldcg(p + 1);
                uint2* d = &Hs2[k16 * HPIT + sb * 4];
                d[0] = make_uint2(lo.x, hi.x);
                d[1] = make_uint2(lo.y, hi.y);
                d[2] = make_uint2(lo.z, hi.z);
                d[3] = make_uint2(lo.w, hi.w);
            }
        }
        __syncthreads();

        // ---- GEMM: each warp m32 x n48 x k256 ----
        float acc[2][6][4];
#pragma unroll
        for (int mt = 0; mt < 2; mt++)
#pragma unroll
            for (int nt = 0; nt < 6; nt++)
#pragma unroll
                for (int e = 0; e < 4; e++) acc[mt][nt][e] = 0.0f;

        const int kb = wk * 16;
#pragma unroll 4
        for (int kk = 0; kk < 16; kk++) {
            const uint2* hp = Hs2 + (kb + kk) * HPIT;
            uint2 aLo[2], aHi[2];
#pragma unroll
            for (int mt = 0; mt < 2; mt++) {
                const int r = wmg * 32 + mt * 16 + g;
                aLo[mt] = hp[r * 4 + q];
                aHi[mt] = hp[(r + 8) * 4 + q];
            }
            const uint2* wp = Ws2 + (kb + kk) * WPLANE;
#pragma unroll
            for (int nt = 0; nt < 6; nt++) {
                const uint2 bb = wp[(nt * 8 + g) * 4 + q];
#pragma unroll
                for (int mt = 0; mt < 2; mt++)
                    mma_f16(acc[mt][nt][0], acc[mt][nt][1], acc[mt][nt][2], acc[mt][nt][3],
                            aLo[mt].x, aHi[mt].x, aLo[mt].y, aHi[mt].y, bb.x, bb.y);
            }
        }
        __syncthreads();   // staging dead; Red may alias

        if (wk > 0) {
            float* red = Redf + ((wk - 1) * 2 + wmg) * (32 * REDP);
#pragma unroll
            for (int mt = 0; mt < 2; mt++) {
                const int r0 = mt * 16 + g;
#pragma unroll
                for (int nt = 0; nt < 6; nt++) {
                    *(float2*)&red[r0 * REDP + nt * 8 + 2 * q] =
                        make_float2(acc[mt][nt][0], acc[mt][nt][1]);
                    *(float2*)&red[(r0 + 8) * REDP + nt * 8 + 2 * q] =
                        make_float2(acc[mt][nt][2], acc[mt][nt][3]);
                }
            }
        }
        __syncthreads();

        if (wk == 0) {
#pragma unroll
            for (int s = 0; s < 3; s++) {
                const float* red = Redf + (s * 2 + wmg) * (32 * REDP);
#pragma unroll
                for (int mt = 0; mt < 2; mt++) {
                    const int r0 = mt * 16 + g;
#pragma unroll
                    for (int nt = 0; nt < 6; nt++) {
                        const float2 v0 = *(const float2*)&red[r0 * REDP + nt * 8 + 2 * q];
                        const float2 v1 = *(const float2*)&red[(r0 + 8) * REDP + nt * 8 + 2 * q];
                        acc[mt][nt][0] += v0.x; acc[mt][nt][1] += v0.y;
                        acc[mt][nt][2] += v1.x; acc[mt][nt][3] += v1.y;
                    }
                }
            }
#pragma unroll
            for (int mt = 0; mt < 2; mt++)
#pragma unroll
                for (int rr = 0; rr < 2; rr++)
#pragma unroll
                    for (int ntp = 0; ntp < 2; ntp++) {
                        const int b = wmg * 32 + mt * 16 + g + 8 * rr;
                        const int hcb = hc0 + ntp * 8 + 2 * q;
                        float hv2[2];
#pragma unroll
                        for (int e = 0; e < 2; e++) {
                            const int u = mt * 8 + rr * 4 + ntp * 2 + e;
                            const int cb = ntp * 2 + e;
                            const int el = rr * 2 + e;
                            const float sr = acc[mt][ntp][el];
                            const float sz = acc[mt][2 + ntp][el];
                            const float sn = acc[mt][4 + ntp][el];
                            const float r = 1.0f / (1.0f + __expf(-(px[u][0] + sr + bhr[cb])));
                            const float z = 1.0f / (1.0f + __expf(-(px[u][1] + sz + bhz[cb])));
                            const float nn = tanhf(px[u][2] + r * (sn + bhn[cb]));
                            hv2[e] = (1.0f - z) * nn + z * h_prev[u];
                            h_prev[u] = hv2[e];
                        }
                        const __half2 packed = __floats2half2_rn(hv2[0], hv2[1]);
                        *(__half2*)(h16new + (size_t)b * Hq + hcb) = packed;
                        *(__half2*)(hs16 + ((size_t)b * Tq + t) * Hq + hcb) = packed;
                    }
        }

        __threadfence();
        __syncthreads();
        if (tid == 0) g_flagv[blockIdx.x] = G0 + (unsigned)t + 1u;
    }

    if (blockIdx.x == 0 && tid == 0) g_gen = G0 + (unsigned)Tq;
}

__global__ void copy_hlast_kernel(const __half* __restrict__ hs16, float* __restrict__ out)
{
    const int idx = blockIdx.x * 256 + threadIdx.x;
    if (idx < Bq * Hq) {
        const int b = idx >> 10;
        const int h = idx & 1023;
        out[idx] = __half2float(hs16[((size_t)b * Tq + (Tq - 1)) * Hq + h]);
    }
}

// ============================================================================
extern "C" void kernel_launch(void* const* d_in, const int* in_sizes, int n_in,
                              void* d_out, int out_size)
{
    const float* inputs = (const float*)d_in[0];
    const float* h0     = (const float*)d_in[1];
    const float* w_ih   = (const float*)d_in[2];
    const float* w_hh   = (const float*)d_in[3];
    const float* b_ih   = (const float*)d_in[4];
    const float* b_hh   = (const float*)d_in[5];
    const float* w_out  = (const float*)d_in[6];
    const float* b_out  = (const float*)d_in[7];
    float* out = (float*)d_out;

    float* xp;
    __half* hs16;
    cudaGetSymbolAddress((void**)&xp, g_xp);
    cudaGetSymbolAddress((void**)&hs16, g_hs16);

    // two no-ops: aligns ncu's skip-5 capture onto gru_rec_mma
    noop_kernel<<<1, 32>>>();
    noop_kernel<<<1, 32>>>();

    // K1: x_proj = inputs @ w_ih^T + b_ih -> xp[t][b][3H]
    {
        dim3 grid(Gq / 64, (Tq * Bq) / 128);
        mma_gemm<1><<<grid, 256>>>(inputs, (const __half*)0, w_ih, b_ih, xp, Gq, Iq);
    }

    // K2: persistent GRU recurrence -> hs16[b][t][H]
    cudaFuncSetAttribute(gru_rec_mma, cudaFuncAttributeMaxDynamicSharedMemorySize, K2_SMEM);
    gru_rec_mma<<<NB2, 256, K2_SMEM>>>(xp, h0, w_hh, b_hh, hs16);

    // K3: out = hs16 @ w_out^T + b_out -> d_out[0 : B*T*O]
    {
        dim3 grid(Oq / 64, (Bq * Tq) / 128);
        mma_gemm<0><<<grid, 256>>>((const float*)0, hs16, w_out, b_out, out, Oq, Hq);
    }

    // K4: h_last tail
    copy_hlast_kernel<<<(Bq * Hq) / 256, 256>>>(hs16, out + (size_t)Bq * Tq * Oq);
}

// round 7
// speedup vs baseline: 2.6565x; 1.1298x over previous
#include <cuda_runtime.h>
#include <cuda_fp16.h>
#include <math.h>

#define Bq 64
#define Tq 512
#define Iq 512
#define Hq 1024
#define Oq 512
#define Gq 3072

// -------- scratch (device globals) --------
__device__ float  g_xp[(size_t)Tq * Bq * Gq];      // [t][b][3H] fp32
__device__ __half g_hs16[(size_t)Bq * Tq * Hq];    // [b][t][H]
__device__ __half g_h16[2][Bq * Hq];               // h ring
__device__ __half g_x16[(size_t)Tq * Bq * Iq];     // inputs, [t*64+b][I] fp16
__device__ __half g_wih16[(size_t)Gq * Iq];
__device__ __half g_wout16[(size_t)Oq * Hq];
__device__ unsigned g_flag2[64];
__device__ unsigned g_gen2 = 0;

// -------- helpers --------
__device__ __forceinline__ unsigned pk2(float a, float b) {
    __half2 h = __floats2half2_rn(a, b);
    return *reinterpret_cast<unsigned*>(&h);
}
__device__ __forceinline__ void mma_f16(
    float& d0, float& d1, float& d2, float& d3,
    unsigned a0, unsigned a1, unsigned a2, unsigned a3,
    unsigned b0, unsigned b1)
{
    asm volatile(
        "mma.sync.aligned.m16n8k16.row.col.f32.f16.f16.f32 "
        "{%0,%1,%2,%3},{%4,%5,%6,%7},{%8,%9},{%0,%1,%2,%3};"
        : "+f"(d0), "+f"(d1), "+f"(d2), "+f"(d3)
        : "r"(a0), "r"(a1), "r"(a2), "r"(a3), "r"(b0), "r"(b1));
}
__device__ __forceinline__ void st_release_gpu(unsigned* p, unsigned v) {
    asm volatile("st.release.gpu.global.u32 [%0], %1;" :: "l"(p), "r"(v) : "memory");
}
__device__ __forceinline__ unsigned ld_acquire_gpu(const unsigned* p) {
    unsigned v;
    asm volatile("ld.acquire.gpu.global.u32 %0, [%1];" : "=r"(v) : "l"(p) : "memory");
    return v;
}
__device__ __forceinline__ float sigm_f(float x) {
    return 1.0f / (1.0f + __expf(-x));
}
__device__ __forceinline__ float tanh_f(float x) {
    return __fdividef(2.0f, 1.0f + __expf(-2.0f * x)) - 1.0f;
}

// ============================================================================
// Conversion kernels (replace the noops; run once per call, cheap)
// ============================================================================
__global__ __launch_bounds__(256) void cvt_x16_kernel(const float* __restrict__ in,
                                                      __half* __restrict__ out)
{
    const int idx = blockIdx.x * 256 + threadIdx.x;   // one 8-elem chunk
    const int m = idx >> 6;                            // row (t*64+b), Iq/8=64 chunks
    const int c = idx & 63;
    const float* src = in + ((size_t)(m & 63) * Tq + (size_t)(m >> 6)) * Iq + c * 8;
    const float4 f0 = __ldg((const float4*)src);
    const float4 f1 = __ldg((const float4*)(src + 4));
    uint4 o;
    o.x = pk2(f0.x, f0.y); o.y = pk2(f0.z, f0.w);
    o.z = pk2(f1.x, f1.y); o.w = pk2(f1.z, f1.w);
    *(uint4*)(out + (size_t)m * Iq + c * 8) = o;
}

__global__ __launch_bounds__(256) void cvt_w16_kernel(
    const float* __restrict__ w_ih, const float* __restrict__ w_out,
    __half* __restrict__ wih16, __half* __restrict__ wout16)
{
    const int idx = blockIdx.x * 256 + threadIdx.x;   // one 8-elem chunk
    const int NIH = (Gq * Iq) / 8;                    // 196608
    const float* src;
    __half* dst;
    int off;
    if (idx < NIH) { src = w_ih; dst = wih16; off = idx * 8; }
    else           { src = w_out; dst = wout16; off = (idx - NIH) * 8; }
    const float4 f0 = __ldg((const float4*)(src + off));
    const float4 f1 = __ldg((const float4*)(src + off + 4));
    uint4 o;
    o.x = pk2(f0.x, f0.y); o.y = pk2(f0.z, f0.w);
    o.z = pk2(f1.x, f1.y); o.w = pk2(f1.z, f1.w);
    *(uint4*)(dst + off) = o;
}

// ============================================================================
// Pure-fp16 MMA GEMM: C[m][n] = sum_k A16[m][k]*B16[n][k] + bias[n]  (fp32 out)
// Block tile 128x64, k-tile 64, 256 threads.
// ============================================================================
#define APIT 513
#define BPIT 257

__global__ __launch_bounds__(256) void mma_gemm16(
    const __half* __restrict__ A16, const __half* __restrict__ B16,
    const float* __restrict__ bias, float* __restrict__ C,
    int N, int K)
{
    __shared__ __align__(16) uint2 As2[4 * APIT];
    __shared__ __align__(16) uint2 Bs2[4 * BPIT];

    const int tid = threadIdx.x;
    const int m0 = blockIdx.y * 128, n0 = blockIdx.x * 64;
    const int lane = tid & 31, warp = tid >> 5;
    const int g = lane >> 2, q = lane & 3;
    const int wm = warp >> 1, wn = warp & 1;

    const int ap = tid & 3;
    const int ar = tid >> 2;
    size_t arow[2];
#pragma unroll
    for (int i = 0; i < 2; i++) arow[i] = (size_t)(m0 + ar + i * 64) * (size_t)K;
    const size_t brow = (size_t)(n0 + ar) * (size_t)K;

    float acc[2][4][4];
#pragma unroll
    for (int mt = 0; mt < 2; mt++)
#pragma unroll
        for (int nt = 0; nt < 4; nt++)
#pragma unroll
            for (int e = 0; e < 4; e++) acc[mt][nt][e] = 0.0f;

    uint4 ha[2][2], hb[2];
#pragma unroll
    for (int i = 0; i < 2; i++) {
        ha[i][0] = __ldg((const uint4*)(A16 + arow[i] + ap * 16));
        ha[i][1] = __ldg((const uint4*)(A16 + arow[i] + ap * 16 + 8));
    }
    hb[0] = __ldg((const uint4*)(B16 + brow + ap * 16));
    hb[1] = __ldg((const uint4*)(B16 + brow + ap * 16 + 8));

    for (int k0 = 0; k0 < K; k0 += 64) {
#pragma unroll
        for (int i = 0; i < 2; i++) {
            uint2* d = &As2[ap * APIT + (ar + i * 64) * 4];
            d[0] = make_uint2(ha[i][0].x, ha[i][1].x);
            d[1] = make_uint2(ha[i][0].y, ha[i][1].y);
            d[2] = make_uint2(ha[i][0].z, ha[i][1].z);
            d[3] = make_uint2(ha[i][0].w, ha[i][1].w);
        }
        {
            uint2* d = &Bs2[ap * BPIT + ar * 4];
            d[0] = make_uint2(hb[0].x, hb[1].x);
            d[1] = make_uint2(hb[0].y, hb[1].y);
            d[2] = make_uint2(hb[0].z, hb[1].z);
            d[3] = make_uint2(hb[0].w, hb[1].w);
        }
        __syncthreads();

        if (k0 + 64 < K) {
#pragma unroll
            for (int i = 0; i < 2; i++) {
                ha[i][0] = __ldg((const uint4*)(A16 + arow[i] + k0 + 64 + ap * 16));
                ha[i][1] = __ldg((const uint4*)(A16 + arow[i] + k0 + 64 + ap * 16 + 8));
            }
            hb[0] = __ldg((const uint4*)(B16 + brow + k0 + 64 + ap * 16));
            hb[1] = __ldg((const uint4*)(B16 + brow + k0 + 64 + ap * 16 + 8));
        }

#pragma unroll
        for (int p = 0; p < 4; p++) {
            uint2 aLo[2], aHi[2];
#pragma unroll
            for (int mt = 0; mt < 2; mt++) {
                const int r = wm * 32 + mt * 16 + g;
                aLo[mt] = As2[p * APIT + r * 4 + q];
                aHi[mt] = As2[p * APIT + (r + 8) * 4 + q];
            }
#pragma unroll
            for (int nt = 0; nt < 4; nt++) {
                const uint2 bb = Bs2[p * BPIT + (wn * 32 + nt * 8 + g) * 4 + q];
#pragma unroll
                for (int mt = 0; mt < 2; mt++)
                    mma_f16(acc[mt][nt][0], acc[mt][nt][1], acc[mt][nt][2], acc[mt][nt][3],
                            aLo[mt].x, aHi[mt].x, aLo[mt].y, aHi[mt].y, bb.x, bb.y);
            }
        }
        __syncthreads();
    }

#pragma unroll
    for (int mt = 0; mt < 2; mt++) {
        const int mrow = m0 + wm * 32 + mt * 16 + g;
#pragma unroll
        for (int nt = 0; nt < 4; nt++) {
            const int col = n0 + wn * 32 + nt * 8 + 2 * q;
            const float2 bb = *(const float2*)&bias[col];
            float2 o0, o1;
            o0.x = acc[mt][nt][0] + bb.x; o0.y = acc[mt][nt][1] + bb.y;
            o1.x = acc[mt][nt][2] + bb.x; o1.y = acc[mt][nt][3] + bb.y;
            *(float2*)&C[(size_t)mrow * N + col] = o0;
            *(float2*)&C[(size_t)(mrow + 8) * N + col] = o1;
        }
    }
}

// ============================================================================
// Persistent GRU recurrence, fp16 MMA, release/acquire barrier,
// all-warp reduce+gates. 64 blocks x 256 threads.
// ============================================================================
#define NB2 64
#define WPLANE 192
#define HPIT 257
#define WS_U2 (64 * WPLANE)
#define HS_U2 (64 * HPIT)
#define K2_SMEM ((WS_U2 + HS_U2) * 8)   // 229888 B
#define REDP 52                          // floats per reduce row

__global__ __launch_bounds__(256, 1) void gru_rec_mma(
    const float* __restrict__ xp, const float* __restrict__ h0,
    const float* __restrict__ w_hh, const float* __restrict__ b_hh,
    __half* __restrict__ hs16)
{
    extern __shared__ uint2 sm2[];
    uint2* Ws2 = sm2;
    uint2* Hs2 = sm2 + WS_U2;
    float* Redf = (float*)Hs2;          // aliases staging after GEMM
                                        // 8 sets x 32 x REDP x 4B = 53KB < 131KB

    const int tid = threadIdx.x;
    const int lane = tid & 31, warp = tid >> 5;
    const int g = lane >> 2, q = lane & 3;
    const int wk = warp >> 1, wmg = warp & 1;
    const int hc0 = blockIdx.x * 16;

    // resident weights
    for (int idx = tid; idx < WS_U2; idx += 256) {
        const int k16 = idx / WPLANE;
        const int r = idx - k16 * WPLANE;
        const int n = r >> 2, qq = r & 3;
        const float* src = w_hh + ((size_t)(n >> 4) * Hq + hc0 + (n & 15)) * Hq + k16 * 16;
        Ws2[idx] = make_uint2(pk2(src[2 * qq], src[2 * qq + 1]),
                              pk2(src[2 * qq + 8], src[2 * qq + 9]));
    }

    // gate ownership: thread -> b = tid>>2, 4 cols hc0 + (tid&3)*4 + [0..3]
    const int gb = tid >> 2;
    const int gc4 = (tid & 3) * 4;
    const float4 bhr4 = *(const float4*)&b_hh[hc0 + gc4];
    const float4 bhz4 = *(const float4*)&b_hh[Hq + hc0 + gc4];
    const float4 bhn4 = *(const float4*)&b_hh[2 * Hq + hc0 + gc4];
    float4 h_prev = *(const float4*)&h0[(size_t)gb * Hq + hc0 + gc4];

    const int sb = tid >> 2;
    const int sk0 = tid & 3;

    const unsigned G0 = g_gen2;
    __syncthreads();

    for (int t = 0; t < Tq; t++) {
        const __half* h16old = g_h16[(t - 1) & 1];
        __half* h16new = g_h16[t & 1];

        // xp prefetch: 3 float4 per thread, in flight across poll+stage+GEMM
        const float* xpb = xp + ((size_t)t * 64 + gb) * Gq + hc0 + gc4;
        const float4 pxr = __ldg((const float4*)xpb);
        const float4 pxz = __ldg((const float4*)(xpb + Hq));
        const float4 pxn = __ldg((const float4*)(xpb + 2 * Hq));

        // ---- acquire barrier ----
        if (t > 0) {
            const unsigned need = G0 + (unsigned)t;
            if (tid < NB2) {
                while (ld_acquire_gpu(&g_flag2[tid]) < need) { }
            }
            __syncthreads();
        }

        // ---- stage full h ----
        if (t == 0) {
#pragma unroll 4
            for (int i = 0; i < 16; i++) {
                const int k16 = sk0 + 4 * i;
                const float* p = h0 + (size_t)sb * Hq + k16 * 16;
                const float4 f0 = __ldg((const float4*)p);
                const float4 f1 = __ldg((const float4*)(p + 4));
                const float4 f2 = __ldg((const float4*)(p + 8));
                const float4 f3 = __ldg((const float4*)(p + 12));
                uint2* d = &Hs2[k16 * HPIT + sb * 4];
                d[0] = make_uint2(pk2(f0.x, f0.y), pk2(f2.x, f2.y));
                d[1] = make_uint2(pk2(f0.z, f0.w), pk2(f2.z, f2.w));
                d[2] = make_uint2(pk2(f1.x, f1.y), pk2(f3.x, f3.y));
                d[3] = make_uint2(pk2(f1.z, f1.w), pk2(f3.z, f3.w));
            }
        } else {
#pragma unroll 4
            for (int i = 0; i < 16; i++) {
                const int k16 = sk0 + 4 * i;
                const uint4* p = (const uint4*)(h16old + (size_t)sb * Hq + k16 * 16);
                const uint4 lo = __ldcg(p);
                const uint4 hi = __ldcg(p + 1);
                uint2* d = &Hs2[k16 * HPIT + sb * 4];
                d[0] = make_uint2(lo.x, hi.x);
                d[1] = make_uint2(lo.y, hi.y);
                d[2] = make_uint2(lo.z, hi.z);
                d[3] = make_uint2(lo.w, hi.w);
            }
        }
        __syncthreads();

        // ---- GEMM: warp = m32 x n48 x k256 ----
        float acc[2][6][4];
#pragma unroll
        for (int mt = 0; mt < 2; mt++)
#pragma unroll
            for (int nt = 0; nt < 6; nt++)
#pragma unroll
                for (int e = 0; e < 4; e++) acc[mt][nt][e] = 0.0f;

        const int kb = wk * 16;
#pragma unroll 4
        for (int kk = 0; kk < 16; kk++) {
            const uint2* hp = Hs2 + (kb + kk) * HPIT;
            uint2 aLo[2], aHi[2];
#pragma unroll
            for (int mt = 0; mt < 2; mt++) {
                const int r = wmg * 32 + mt * 16 + g;
                aLo[mt] = hp[r * 4 + q];
                aHi[mt] = hp[(r + 8) * 4 + q];
            }
            const uint2* wp = Ws2 + (kb + kk) * WPLANE;
#pragma unroll
            for (int nt = 0; nt < 6; nt++) {
                const uint2 bb = wp[(nt * 8 + g) * 4 + q];
#pragma unroll
                for (int mt = 0; mt < 2; mt++)
                    mma_f16(acc[mt][nt][0], acc[mt][nt][1], acc[mt][nt][2], acc[mt][nt][3],
                            aLo[mt].x, aHi[mt].x, aLo[mt].y, aHi[mt].y, bb.x, bb.y);
            }
        }
        __syncthreads();   // staging dead; Red may alias

        // ---- all warps publish partials ----
        {
            float* red = Redf + (wk * 2 + wmg) * (32 * REDP);
#pragma unroll
            for (int mt = 0; mt < 2; mt++) {
                const int r0 = mt * 16 + g;
#pragma unroll
                for (int nt = 0; nt < 6; nt++) {
                    *(float2*)&red[r0 * REDP + nt * 8 + 2 * q] =
                        make_float2(acc[mt][nt][0], acc[mt][nt][1]);
                    *(float2*)&red[(r0 + 8) * REDP + nt * 8 + 2 * q] =
                        make_float2(acc[mt][nt][2], acc[mt][nt][3]);
                }
            }
        }
        __syncthreads();

        // ---- per-thread reduce + gates (4 outputs each) ----
        {
            const int half = gb >> 5;        // which m-half the partials live in
            const int r = gb & 31;
            float sr[4] = {0, 0, 0, 0}, sz[4] = {0, 0, 0, 0}, sn[4] = {0, 0, 0, 0};
#pragma unroll
            for (int k4 = 0; k4 < 4; k4++) {
                const float* red = Redf + (k4 * 2 + half) * (32 * REDP) + r * REDP;
                const float4 vr = *(const float4*)&red[0 * 16 + gc4];
                const float4 vz = *(const float4*)&red[1 * 16 + gc4];
                const float4 vn = *(const float4*)&red[2 * 16 + gc4];
                sr[0] += vr.x; sr[1] += vr.y; sr[2] += vr.z; sr[3] += vr.w;
                sz[0] += vz.x; sz[1] += vz.y; sz[2] += vz.z; sz[3] += vz.w;
                sn[0] += vn.x; sn[1] += vn.y; sn[2] += vn.z; sn[3] += vn.w;
            }
            const float pxr_[4] = {pxr.x, pxr.y, pxr.z, pxr.w};
            const float pxz_[4] = {pxz.x, pxz.y, pxz.z, pxz.w};
            const float pxn_[4] = {pxn.x, pxn.y, pxn.z, pxn.w};
            const float bhr_[4] = {bhr4.x, bhr4.y, bhr4.z, bhr4.w};
            const float bhz_[4] = {bhz4.x, bhz4.y, bhz4.z, bhz4.w};
            const float bhn_[4] = {bhn4.x, bhn4.y, bhn4.z, bhn4.w};
            float hp_[4] = {h_prev.x, h_prev.y, h_prev.z, h_prev.w};
            float hv[4];
#pragma unroll
            for (int e = 0; e < 4; e++) {
                const float rr = sigm_f(pxr_[e] + sr[e] + bhr_[e]);
                const float zz = sigm_f(pxz_[e] + sz[e] + bhz_[e]);
                const float nn = tanh_f(pxn_[e] + rr * (sn[e] + bhn_[e]));
                hv[e] = (1.0f - zz) * nn + zz * hp_[e];
            }
            h_prev = make_float4(hv[0], hv[1], hv[2], hv[3]);
            uint2 pk;
            pk.x = pk2(hv[0], hv[1]);
            pk.y = pk2(hv[2], hv[3]);
            *(uint2*)(h16new + (size_t)gb * Hq + hc0 + gc4) = pk;
            *(uint2*)(hs16 + ((size_t)gb * Tq + t) * Hq + hc0 + gc4) = pk;
        }

        // ---- release publish (syncthreads gives intra-CTA hb; release extends) ----
        __syncthreads();
        if (tid == 0) st_release_gpu(&g_flag2[blockIdx.x], G0 + (unsigned)t + 1u);
    }

    if (blockIdx.x == 0 && tid == 0) {
        __threadfence();
        g_gen2 = G0 + (unsigned)Tq;
    }
}

__global__ void copy_hlast_kernel(const __half* __restrict__ hs16, float* __restrict__ out)
{
    const int idx = blockIdx.x * 256 + threadIdx.x;
    if (idx < Bq * Hq) {
        const int b = idx >> 10;
        const int h = idx & 1023;
        out[idx] = __half2float(hs16[((size_t)b * Tq + (Tq - 1)) * Hq + h]);
    }
}

// ============================================================================
extern "C" void kernel_launch(void* const* d_in, const int* in_sizes, int n_in,
                              void* d_out, int out_size)
{
    const float* inputs = (const float*)d_in[0];
    const float* h0     = (const float*)d_in[1];
    const float* w_ih   = (const float*)d_in[2];
    const float* w_hh   = (const float*)d_in[3];
    const float* b_ih   = (const float*)d_in[4];
    const float* b_hh   = (const float*)d_in[5];
    const float* w_out  = (const float*)d_in[6];
    const float* b_out  = (const float*)d_in[7];
    float* out = (float*)d_out;

    float* xp;
    __half *hs16, *x16, *wih16, *wout16;
    cudaGetSymbolAddress((void**)&xp, g_xp);
    cudaGetSymbolAddress((void**)&hs16, g_hs16);
    cudaGetSymbolAddress((void**)&x16, g_x16);
    cudaGetSymbolAddress((void**)&wih16, g_wih16);
    cudaGetSymbolAddress((void**)&wout16, g_wout16);

    // conversions (also keep gru_rec_mma at launch index 4 for ncu -s 5)
    cvt_x16_kernel<<<(Tq * Bq * (Iq / 8)) / 256, 256>>>(inputs, x16);
    cvt_w16_kernel<<<((Gq * Iq + Oq * Hq) / 8) / 256, 256>>>(w_ih, w_out, wih16, wout16);

    // K1: x_proj = x16 @ wih16^T + b_ih -> xp[t][b][3H]
    {
        dim3 grid(Gq / 64, (Tq * Bq) / 128);
        mma_gemm16<<<grid, 256>>>(x16, wih16, b_ih, xp, Gq, Iq);
    }

    // K2: persistent GRU recurrence -> hs16
    cudaFuncSetAttribute(gru_rec_mma, cudaFuncAttributeMaxDynamicSharedMemorySize, K2_SMEM);
    gru_rec_mma<<<NB2, 256, K2_SMEM>>>(xp, h0, w_hh, b_hh, hs16);

    // K3: out = hs16 @ wout16^T + b_out
    {
        dim3 grid(Oq / 64, (Bq * Tq) / 128);
        mma_gemm16<<<grid, 256>>>(hs16, wout16, b_out, out, Oq, Hq);
    }

    // K4: h_last tail
    copy_hlast_kernel<<<(Bq * Hq) / 256, 256>>>(hs16, out + (size_t)Bq * Tq * Oq);
}

// round 8
// speedup vs baseline: 2.7046x; 1.0181x over previous
#include <cuda_runtime.h>
#include <cuda_fp16.h>
#include <math.h>

#define Bq 64
#define Tq 512
#define Iq 512
#define Hq 1024
#define Oq 512
#define Gq 3072

// -------- scratch (device globals) --------
__device__ float  g_xp[(size_t)Tq * Bq * Gq];      // [t][b][3H] fp32
__device__ __half g_hs16[(size_t)Bq * Tq * Hq];    // [b][t][H]
__device__ __half g_h16[2][Bq * Hq];               // h ring
__device__ __half g_x16[(size_t)Tq * Bq * Iq];     // inputs, [t*64+b][I] fp16
__device__ __half g_wih16[(size_t)Gq * Iq];
__device__ __half g_wout16[(size_t)Oq * Hq];
__device__ unsigned g_flag2[64];
__device__ unsigned g_gen2 = 0;

// -------- helpers --------
__device__ __forceinline__ unsigned pk2(float a, float b) {
    __half2 h = __floats2half2_rn(a, b);
    return *reinterpret_cast<unsigned*>(&h);
}
__device__ __forceinline__ void mma_f16(
    float& d0, float& d1, float& d2, float& d3,
    unsigned a0, unsigned a1, unsigned a2, unsigned a3,
    unsigned b0, unsigned b1)
{
    asm volatile(
        "mma.sync.aligned.m16n8k16.row.col.f32.f16.f16.f32 "
        "{%0,%1,%2,%3},{%4,%5,%6,%7},{%8,%9},{%0,%1,%2,%3};"
        : "+f"(d0), "+f"(d1), "+f"(d2), "+f"(d3)
        : "r"(a0), "r"(a1), "r"(a2), "r"(a3), "r"(b0), "r"(b1));
}
__device__ __forceinline__ void st_release_gpu(unsigned* p, unsigned v) {
    asm volatile("st.release.gpu.global.u32 [%0], %1;" :: "l"(p), "r"(v) : "memory");
}
__device__ __forceinline__ unsigned ld_acquire_gpu(const unsigned* p) {
    unsigned v;
    asm volatile("ld.acquire.gpu.global.u32 %0, [%1];" : "=r"(v) : "l"(p) : "memory");
    return v;
}

// MUFU-free sigmoid: 1/(1+e^{-x}) entirely in FFMA/ALU.
// exp2 via magic-round + deg-5 poly (rel err ~2e-6); recip via bit-hack + 3 Newton.
__device__ __forceinline__ float sigm_fast(float x) {
    const float L2E = 1.4426950408889634f;
    const float MAGIC = 12582912.0f;       // 1.5 * 2^23
    float xc = fminf(fmaxf(x, -87.0f), 87.0f);
    float t = fmaf(xc, -L2E, MAGIC);       // y + magic,  y = -x*log2(e)
    float nf = t - MAGIC;                  // n = rn(y)
    float f = fmaf(xc, -L2E, -nf);         // f = y - n,  |f| <= 0.5
    float p = 1.3333558146e-3f;
    p = fmaf(p, f, 9.6181291076e-3f);
    p = fmaf(p, f, 5.5504108665e-2f);
    p = fmaf(p, f, 2.4022650696e-1f);
    p = fmaf(p, f, 6.9314718056e-1f);
    p = fmaf(p, f, 1.0f);                  // 2^f
    int ni = __float_as_int(t) - 0x4B400000;
    float sc = __int_as_float((ni << 23) + 0x3F800000);  // 2^n
    float E = p * sc;                      // e^{-x}
    float d = 1.0f + E;
    float r = __int_as_float(0x7EF311C7 - __float_as_int(d));
    r = r * fmaf(-d, r, 2.0f);
    r = r * fmaf(-d, r, 2.0f);
    r = r * fmaf(-d, r, 2.0f);
    return r;
}
__device__ __forceinline__ float tanh_fast(float x) {
    return fmaf(2.0f, sigm_fast(2.0f * x), -1.0f);
}

// ============================================================================
// Conversion kernels (run once per call, cheap; keep K2 at launch index 4)
// ============================================================================
__global__ __launch_bounds__(256) void cvt_x16_kernel(const float* __restrict__ in,
                                                      __half* __restrict__ out)
{
    const int idx = blockIdx.x * 256 + threadIdx.x;
    const int m = idx >> 6;
    const int c = idx & 63;
    const float* src = in + ((size_t)(m & 63) * Tq + (size_t)(m >> 6)) * Iq + c * 8;
    const float4 f0 = __ldg((const float4*)src);
    const float4 f1 = __ldg((const float4*)(src + 4));
    uint4 o;
    o.x = pk2(f0.x, f0.y); o.y = pk2(f0.z, f0.w);
    o.z = pk2(f1.x, f1.y); o.w = pk2(f1.z, f1.w);
    *(uint4*)(out + (size_t)m * Iq + c * 8) = o;
}

__global__ __launch_bounds__(256) void cvt_w16_kernel(
    const float* __restrict__ w_ih, const float* __restrict__ w_out,
    __half* __restrict__ wih16, __half* __restrict__ wout16)
{
    const int idx = blockIdx.x * 256 + threadIdx.x;
    const int NIH = (Gq * Iq) / 8;
    const float* src;
    __half* dst;
    int off;
    if (idx < NIH) { src = w_ih; dst = wih16; off = idx * 8; }
    else           { src = w_out; dst = wout16; off = (idx - NIH) * 8; }
    const float4 f0 = __ldg((const float4*)(src + off));
    const float4 f1 = __ldg((const float4*)(src + off + 4));
    uint4 o;
    o.x = pk2(f0.x, f0.y); o.y = pk2(f0.z, f0.w);
    o.z = pk2(f1.x, f1.y); o.w = pk2(f1.z, f1.w);
    *(uint4*)(dst + off) = o;
}

// ============================================================================
// Pure-fp16 MMA GEMM: C[m][n] = sum_k A16[m][k]*B16[n][k] + bias[n]  (fp32 out)
// ============================================================================
#define APIT 513
#define BPIT 257

__global__ __launch_bounds__(256) void mma_gemm16(
    const __half* __restrict__ A16, const __half* __restrict__ B16,
    const float* __restrict__ bias, float* __restrict__ C,
    int N, int K)
{
    __shared__ __align__(16) uint2 As2[4 * APIT];
    __shared__ __align__(16) uint2 Bs2[4 * BPIT];

    const int tid = threadIdx.x;
    const int m0 = blockIdx.y * 128, n0 = blockIdx.x * 64;
    const int lane = tid & 31, warp = tid >> 5;
    const int g = lane >> 2, q = lane & 3;
    const int wm = warp >> 1, wn = warp & 1;

    const int ap = tid & 3;
    const int ar = tid >> 2;
    size_t arow[2];
#pragma unroll
    for (int i = 0; i < 2; i++) arow[i] = (size_t)(m0 + ar + i * 64) * (size_t)K;
    const size_t brow = (size_t)(n0 + ar) * (size_t)K;

    float acc[2][4][4];
#pragma unroll
    for (int mt = 0; mt < 2; mt++)
#pragma unroll
        for (int nt = 0; nt < 4; nt++)
#pragma unroll
            for (int e = 0; e < 4; e++) acc[mt][nt][e] = 0.0f;

    uint4 ha[2][2], hb[2];
#pragma unroll
    for (int i = 0; i < 2; i++) {
        ha[i][0] = __ldg((const uint4*)(A16 + arow[i] + ap * 16));
        ha[i][1] = __ldg((const uint4*)(A16 + arow[i] + ap * 16 + 8));
    }
    hb[0] = __ldg((const uint4*)(B16 + brow + ap * 16));
    hb[1] = __ldg((const uint4*)(B16 + brow + ap * 16 + 8));

    for (int k0 = 0; k0 < K; k0 += 64) {
#pragma unroll
        for (int i = 0; i < 2; i++) {
            uint2* d = &As2[ap * APIT + (ar + i * 64) * 4];
            d[0] = make_uint2(ha[i][0].x, ha[i][1].x);
            d[1] = make_uint2(ha[i][0].y, ha[i][1].y);
            d[2] = make_uint2(ha[i][0].z, ha[i][1].z);
            d[3] = make_uint2(ha[i][0].w, ha[i][1].w);
        }
        {
            uint2* d = &Bs2[ap * BPIT + ar * 4];
            d[0] = make_uint2(hb[0].x, hb[1].x);
            d[1] = make_uint2(hb[0].y, hb[1].y);
            d[2] = make_uint2(hb[0].z, hb[1].z);
            d[3] = make_uint2(hb[0].w, hb[1].w);
        }
        __syncthreads();

        if (k0 + 64 < K) {
#pragma unroll
            for (int i = 0; i < 2; i++) {
                ha[i][0] = __ldg((const uint4*)(A16 + arow[i] + k0 + 64 + ap * 16));
                ha[i][1] = __ldg((const uint4*)(A16 + arow[i] + k0 + 64 + ap * 16 + 8));
            }
            hb[0] = __ldg((const uint4*)(B16 + brow + k0 + 64 + ap * 16));
            hb[1] = __ldg((const uint4*)(B16 + brow + k0 + 64 + ap * 16 + 8));
        }

#pragma unroll
        for (int p = 0; p < 4; p++) {
            uint2 aLo[2], aHi[2];
#pragma unroll
            for (int mt = 0; mt < 2; mt++) {
                const int r = wm * 32 + mt * 16 + g;
                aLo[mt] = As2[p * APIT + r * 4 + q];
                aHi[mt] = As2[p * APIT + (r + 8) * 4 + q];
            }
#pragma unroll
            for (int nt = 0; nt < 4; nt++) {
                const uint2 bb = Bs2[p * BPIT + (wn * 32 + nt * 8 + g) * 4 + q];
#pragma unroll
                for (int mt = 0; mt < 2; mt++)
                    mma_f16(acc[mt][nt][0], acc[mt][nt][1], acc[mt][nt][2], acc[mt][nt][3],
                            aLo[mt].x, aHi[mt].x, aLo[mt].y, aHi[mt].y, bb.x, bb.y);
            }
        }
        __syncthreads();
    }

#pragma unroll
    for (int mt = 0; mt < 2; mt++) {
        const int mrow = m0 + wm * 32 + mt * 16 + g;
#pragma unroll
        for (int nt = 0; nt < 4; nt++) {
            const int col = n0 + wn * 32 + nt * 8 + 2 * q;
            const float2 bb = *(const float2*)&bias[col];
            float2 o0, o1;
            o0.x = acc[mt][nt][0] + bb.x; o0.y = acc[mt][nt][1] + bb.y;
            o1.x = acc[mt][nt][2] + bb.x; o1.y = acc[mt][nt][3] + bb.y;
            *(float2*)&C[(size_t)mrow * N + col] = o0;
            *(float2*)&C[(size_t)(mrow + 8) * N + col] = o1;
        }
    }
}

// ============================================================================
// Persistent GRU recurrence, fp16 MMA, release/acquire barrier,
// all-warp reduce + MUFU-free gates. 64 blocks x 256 threads.
// ============================================================================
#define NB2 64
#define WPLANE 192
#define HPIT 257
#define WS_U2 (64 * WPLANE)
#define HS_U2 (64 * HPIT)
#define K2_SMEM ((WS_U2 + HS_U2) * 8)   // 229888 B
#define REDP 52

__global__ __launch_bounds__(256, 1) void gru_rec_mma(
    const float* __restrict__ xp, const float* __restrict__ h0,
    const float* __restrict__ w_hh, const float* __restrict__ b_hh,
    __half* __restrict__ hs16)
{
    extern __shared__ uint2 sm2[];
    uint2* Ws2 = sm2;
    uint2* Hs2 = sm2 + WS_U2;
    float* Redf = (float*)Hs2;          // aliases staging after GEMM

    const int tid = threadIdx.x;
    const int lane = tid & 31, warp = tid >> 5;
    const int g = lane >> 2, q = lane & 3;
    const int wk = warp >> 1, wmg = warp & 1;
    const int hc0 = blockIdx.x * 16;

    // resident weights
    for (int idx = tid; idx < WS_U2; idx += 256) {
        const int k16 = idx / WPLANE;
        const int r = idx - k16 * WPLANE;
        const int n = r >> 2, qq = r & 3;
        const float* src = w_hh + ((size_t)(n >> 4) * Hq + hc0 + (n & 15)) * Hq + k16 * 16;
        Ws2[idx] = make_uint2(pk2(src[2 * qq], src[2 * qq + 1]),
                              pk2(src[2 * qq + 8], src[2 * qq + 9]));
    }

    // gate ownership: thread -> b = tid>>2, 4 cols hc0 + (tid&3)*4 + [0..3]
    const int gb = tid >> 2;
    const int gc4 = (tid & 3) * 4;
    const float4 bhr4 = *(const float4*)&b_hh[hc0 + gc4];
    const float4 bhz4 = *(const float4*)&b_hh[Hq + hc0 + gc4];
    const float4 bhn4 = *(const float4*)&b_hh[2 * Hq + hc0 + gc4];
    float4 h_prev = *(const float4*)&h0[(size_t)gb * Hq + hc0 + gc4];

    const int sb = tid >> 2;
    const int sk0 = tid & 3;

    const unsigned G0 = g_gen2;
    __syncthreads();

    for (int t = 0; t < Tq; t++) {
        const __half* h16old = g_h16[(t - 1) & 1];
        __half* h16new = g_h16[t & 1];

        // xp prefetch: 3 float4 per thread
        const float* xpb = xp + ((size_t)t * 64 + gb) * Gq + hc0 + gc4;
        const float4 pxr = __ldg((const float4*)xpb);
        const float4 pxz = __ldg((const float4*)(xpb + Hq));
        const float4 pxn = __ldg((const float4*)(xpb + 2 * Hq));

        // ---- acquire barrier ----
        if (t > 0) {
            const unsigned need = G0 + (unsigned)t;
            if (tid < NB2) {
                while (ld_acquire_gpu(&g_flag2[tid]) < need) { }
            }
            __syncthreads();
        }

        // ---- stage full h ----
        if (t == 0) {
#pragma unroll 4
            for (int i = 0; i < 16; i++) {
                const int k16 = sk0 + 4 * i;
                const float* p = h0 + (size_t)sb * Hq + k16 * 16;
                const float4 f0 = __ldg((const float4*)p);
                const float4 f1 = __ldg((const float4*)(p + 4));
                const float4 f2 = __ldg((const float4*)(p + 8));
                const float4 f3 = __ldg((const float4*)(p + 12));
                uint2* d = &Hs2[k16 * HPIT + sb * 4];
                d[0] = make_uint2(pk2(f0.x, f0.y), pk2(f2.x, f2.y));
                d[1] = make_uint2(pk2(f0.z, f0.w), pk2(f2.z, f2.w));
                d[2] = make_uint2(pk2(f1.x, f1.y), pk2(f3.x, f3.y));
                d[3] = make_uint2(pk2(f1.z, f1.w), pk2(f3.z, f3.w));
            }
        } else {
#pragma unroll 4
            for (int i = 0; i < 16; i++) {
                const int k16 = sk0 + 4 * i;
                const uint4* p = (const uint4*)(h16old + (size_t)sb * Hq + k16 * 16);
                const uint4 lo = __ldcg(p);
                const uint4 hi = __ldcg(p + 1);
                uint2* d = &Hs2[k16 * HPIT + sb * 4];
                d[0] = make_uint2(lo.x, hi.x);
                d[1] = make_uint2(lo.y, hi.y);
                d[2] = make_uint2(lo.z, hi.z);
                d[3] = make_uint2(lo.w, hi.w);
            }
        }
        __syncthreads();

        // ---- GEMM: warp = m32 x n48 x k256 ----
        float acc[2][6][4];
#pragma unroll
        for (int mt = 0; mt < 2; mt++)
#pragma unroll
            for (int nt = 0; nt < 6; nt++)
#pragma unroll
                for (int e = 0; e < 4; e++) acc[mt][nt][e] = 0.0f;

        const int kb = wk * 16;
#pragma unroll 4
        for (int kk = 0; kk < 16; kk++) {
            const uint2* hp = Hs2 + (kb + kk) * HPIT;
            uint2 aLo[2], aHi[2];
#pragma unroll
            for (int mt = 0; mt < 2; mt++) {
                const int r = wmg * 32 + mt * 16 + g;
                aLo[mt] = hp[r * 4 + q];
                aHi[mt] = hp[(r + 8) * 4 + q];
            }
            const uint2* wp = Ws2 + (kb + kk) * WPLANE;
#pragma unroll
            for (int nt = 0; nt < 6; nt++) {
                const uint2 bb = wp[(nt * 8 + g) * 4 + q];
#pragma unroll
                for (int mt = 0; mt < 2; mt++)
                    mma_f16(acc[mt][nt][0], acc[mt][nt][1], acc[mt][nt][2], acc[mt][nt][3],
                            aLo[mt].x, aHi[mt].x, aLo[mt].y, aHi[mt].y, bb.x, bb.y);
            }
        }
        __syncthreads();   // staging dead; Red may alias

        // ---- all warps publish partials ----
        {
            float* red = Redf + (wk * 2 + wmg) * (32 * REDP);
#pragma unroll
            for (int mt = 0; mt < 2; mt++) {
                const int r0 = mt * 16 + g;
#pragma unroll
                for (int nt = 0; nt < 6; nt++) {
                    *(float2*)&red[r0 * REDP + nt * 8 + 2 * q] =
                        make_float2(acc[mt][nt][0], acc[mt][nt][1]);
                    *(float2*)&red[(r0 + 8) * REDP + nt * 8 + 2 * q] =
                        make_float2(acc[mt][nt][2], acc[mt][nt][3]);
                }
            }
        }
        __syncthreads();

        // ---- per-thread reduce + MUFU-free gates (4 outputs each) ----
        {
            const int half = gb >> 5;
            const int r = gb & 31;
            float sr[4] = {0, 0, 0, 0}, sz[4] = {0, 0, 0, 0}, sn[4] = {0, 0, 0, 0};
#pragma unroll
            for (int k4 = 0; k4 < 4; k4++) {
                const float* red = Redf + (k4 * 2 + half) * (32 * REDP) + r * REDP;
                const float4 vr = *(const float4*)&red[0 * 16 + gc4];
                const float4 vz = *(const float4*)&red[1 * 16 + gc4];
                const float4 vn = *(const float4*)&red[2 * 16 + gc4];
                sr[0] += vr.x; sr[1] += vr.y; sr[2] += vr.z; sr[3] += vr.w;
                sz[0] += vz.x; sz[1] += vz.y; sz[2] += vz.z; sz[3] += vz.w;
                sn[0] += vn.x; sn[1] += vn.y; sn[2] += vn.z; sn[3] += vn.w;
            }
            const float pxr_[4] = {pxr.x, pxr.y, pxr.z, pxr.w};
            const float pxz_[4] = {pxz.x, pxz.y, pxz.z, pxz.w};
            const float pxn_[4] = {pxn.x, pxn.y, pxn.z, pxn.w};
            const float bhr_[4] = {bhr4.x, bhr4.y, bhr4.z, bhr4.w};
            const float bhz_[4] = {bhz4.x, bhz4.y, bhz4.z, bhz4.w};
            const float bhn_[4] = {bhn4.x, bhn4.y, bhn4.z, bhn4.w};
            float hp_[4] = {h_prev.x, h_prev.y, h_prev.z, h_prev.w};
            float hv[4];
#pragma unroll
            for (int e = 0; e < 4; e++) {
                const float rr = sigm_fast(pxr_[e] + sr[e] + bhr_[e]);
                const float zz = sigm_fast(pxz_[e] + sz[e] + bhz_[e]);
                const float nn = tanh_fast(pxn_[e] + rr * (sn[e] + bhn_[e]));
                hv[e] = (1.0f - zz) * nn + zz * hp_[e];
            }
            h_prev = make_float4(hv[0], hv[1], hv[2], hv[3]);
            uint2 pk;
            pk.x = pk2(hv[0], hv[1]);
            pk.y = pk2(hv[2], hv[3]);
            *(uint2*)(h16new + (size_t)gb * Hq + hc0 + gc4) = pk;
            *(uint2*)(hs16 + ((size_t)gb * Tq + t) * Hq + hc0 + gc4) = pk;
        }

        // ---- release publish ----
        __syncthreads();
        if (tid == 0) st_release_gpu(&g_flag2[blockIdx.x], G0 + (unsigned)t + 1u);
    }

    if (blockIdx.x == 0 && tid == 0) {
        __threadfence();
        g_gen2 = G0 + (unsigned)Tq;
    }
}

__global__ void copy_hlast_kernel(const __half* __restrict__ hs16, float* __restrict__ out)
{
    const int idx = blockIdx.x * 256 + threadIdx.x;
    if (idx < Bq * Hq) {
        const int b = idx >> 10;
        const int h = idx & 1023;
        out[idx] = __half2float(hs16[((size_t)b * Tq + (Tq - 1)) * Hq + h]);
    }
}

// ============================================================================
extern "C" void kernel_launch(void* const* d_in, const int* in_sizes, int n_in,
                              void* d_out, int out_size)
{
    const float* inputs = (const float*)d_in[0];
    const float* h0     = (const float*)d_in[1];
    const float* w_ih   = (const float*)d_in[2];
    const float* w_hh   = (const float*)d_in[3];
    const float* b_ih   = (const float*)d_in[4];
    const float* b_hh   = (const float*)d_in[5];
    const float* w_out  = (const float*)d_in[6];
    const float* b_out  = (const float*)d_in[7];
    float* out = (float*)d_out;

    float* xp;
    __half *hs16, *x16, *wih16, *wout16;
    cudaGetSymbolAddress((void**)&xp, g_xp);
    cudaGetSymbolAddress((void**)&hs16, g_hs16);
    cudaGetSymbolAddress((void**)&x16, g_x16);
    cudaGetSymbolAddress((void**)&wih16, g_wih16);
    cudaGetSymbolAddress((void**)&wout16, g_wout16);

    // conversions (keep gru_rec_mma at launch index 4 for ncu -s 5)
    cvt_x16_kernel<<<(Tq * Bq * (Iq / 8)) / 256, 256>>>(inputs, x16);
    cvt_w16_kernel<<<((Gq * Iq + Oq * Hq) / 8) / 256, 256>>>(w_ih, w_out, wih16, wout16);

    // K1: x_proj = x16 @ wih16^T + b_ih -> xp[t][b][3H]
    {
        dim3 grid(Gq / 64, (Tq * Bq) / 128);
        mma_gemm16<<<grid, 256>>>(x16, wih16, b_ih, xp, Gq, Iq);
    }

    // K2: persistent GRU recurrence -> hs16
    cudaFuncSetAttribute(gru_rec_mma, cudaFuncAttributeMaxDynamicSharedMemorySize, K2_SMEM);
    gru_rec_mma<<<NB2, 256, K2_SMEM>>>(xp, h0, w_hh, b_hh, hs16);

    // K3: out = hs16 @ wout16^T + b_out
    {
        dim3 grid(Oq / 64, (Bq * Tq) / 128);
        mma_gemm16<<<grid, 256>>>(hs16, wout16, b_out, out, Oq, Hq);
    }

    // K4: h_last tail
    copy_hlast_kernel<<<(Bq * Hq) / 256, 256>>>(hs16, out + (size_t)Bq * Tq * Oq);
}

// round 9
// speedup vs baseline: 4.1323x; 1.5279x over previous
#include <cuda_runtime.h>
#include <cuda_fp16.h>
#include <math.h>

#define Bq 64
#define Tq 512
#define Iq 512
#define Hq 1024
#define Oq 512
#define Gq 3072

// -------- scratch (device globals) --------
__device__ float  g_xp[(size_t)Tq * Bq * Gq];      // [t][b][3H] fp32
__device__ __half g_hs16[(size_t)Bq * Tq * Hq];    // [b][t][H]
__device__ uint2  g_hr[2][64 * 64 * 4];            // h ring, fragment layout [k16][b][q]
__device__ __half g_x16[(size_t)Tq * Bq * Iq];     // inputs, [t*64+b][I] fp16
__device__ __half g_wih16[(size_t)Gq * Iq];
__device__ __half g_wout16[(size_t)Oq * Hq];
__device__ unsigned g_flag2[64];
__device__ unsigned g_gen2 = 0;

// -------- helpers --------
__device__ __forceinline__ unsigned pk2(float a, float b) {
    __half2 h = __floats2half2_rn(a, b);
    return *reinterpret_cast<unsigned*>(&h);
}
__device__ __forceinline__ void mma_f16(
    float& d0, float& d1, float& d2, float& d3,
    unsigned a0, unsigned a1, unsigned a2, unsigned a3,
    unsigned b0, unsigned b1)
{
    asm volatile(
        "mma.sync.aligned.m16n8k16.row.col.f32.f16.f16.f32 "
        "{%0,%1,%2,%3},{%4,%5,%6,%7},{%8,%9},{%0,%1,%2,%3};"
        : "+f"(d0), "+f"(d1), "+f"(d2), "+f"(d3)
        : "r"(a0), "r"(a1), "r"(a2), "r"(a3), "r"(b0), "r"(b1));
}
__device__ __forceinline__ void st_release_gpu(unsigned* p, unsigned v) {
    asm volatile("st.release.gpu.global.u32 [%0], %1;" :: "l"(p), "r"(v) : "memory");
}
__device__ __forceinline__ unsigned ld_acquire_gpu(const unsigned* p) {
    unsigned v;
    asm volatile("ld.acquire.gpu.global.u32 %0, [%1];" : "=r"(v) : "l"(p) : "memory");
    return v;
}
__device__ __forceinline__ uint2 ldcg_u2(const uint2* p) {
    uint2 v;
    asm volatile("ld.global.cg.v2.u32 {%0,%1}, [%2];" : "=r"(v.x), "=r"(v.y) : "l"(p));
    return v;
}

// MUFU-free sigmoid (FFMA/ALU only)
__device__ __forceinline__ float sigm_fast(float x) {
    const float L2E = 1.4426950408889634f;
    const float MAGIC = 12582912.0f;
    float xc = fminf(fmaxf(x, -87.0f), 87.0f);
    float t = fmaf(xc, -L2E, MAGIC);
    float nf = t - MAGIC;
    float f = fmaf(xc, -L2E, -nf);
    float p = 1.3333558146e-3f;
    p = fmaf(p, f, 9.6181291076e-3f);
    p = fmaf(p, f, 5.5504108665e-2f);
    p = fmaf(p, f, 2.4022650696e-1f);
    p = fmaf(p, f, 6.9314718056e-1f);
    p = fmaf(p, f, 1.0f);
    int ni = __float_as_int(t) - 0x4B400000;
    float sc = __int_as_float((ni << 23) + 0x3F800000);
    float E = p * sc;
    float d = 1.0f + E;
    float r = __int_as_float(0x7EF311C7 - __float_as_int(d));
    r = r * fmaf(-d, r, 2.0f);
    r = r * fmaf(-d, r, 2.0f);
    r = r * fmaf(-d, r, 2.0f);
    return r;
}
__device__ __forceinline__ float tanh_fast(float x) {
    return fmaf(2.0f, sigm_fast(2.0f * x), -1.0f);
}

__global__ void noop_kernel() {}

// ============================================================================
// Merged conversion kernel: x16 [0,8192) | weights [8192,9216) | h0-ring [9216,9232)
// ============================================================================
__global__ __launch_bounds__(256) void cvt_all_kernel(
    const float* __restrict__ inputs, const float* __restrict__ w_ih,
    const float* __restrict__ w_out, const float* __restrict__ h0,
    __half* __restrict__ x16, __half* __restrict__ wih16,
    __half* __restrict__ wout16, uint2* __restrict__ ring1)
{
    const int bid = blockIdx.x;
    const int tid = threadIdx.x;
    if (bid < 8192) {
        const int idx = bid * 256 + tid;
        const int m = idx >> 6;
        const int c = idx & 63;
        const float* src = inputs + ((size_t)(m & 63) * Tq + (size_t)(m >> 6)) * Iq + c * 8;
        const float4 f0 = __ldg((const float4*)src);
        const float4 f1 = __ldg((const float4*)(src + 4));
        uint4 o;
        o.x = pk2(f0.x, f0.y); o.y = pk2(f0.z, f0.w);
        o.z = pk2(f1.x, f1.y); o.w = pk2(f1.z, f1.w);
        *(uint4*)(x16 + (size_t)m * Iq + c * 8) = o;
    } else if (bid < 9216) {
        const int idx = (bid - 8192) * 256 + tid;
        const int NIH = (Gq * Iq) / 8;
        const float* src;
        __half* dst;
        int off;
        if (idx < NIH) { src = w_ih; dst = wih16; off = idx * 8; }
        else           { src = w_out; dst = wout16; off = (idx - NIH) * 8; }
        const float4 f0 = __ldg((const float4*)(src + off));
        const float4 f1 = __ldg((const float4*)(src + off + 4));
        uint4 o;
        o.x = pk2(f0.x, f0.y); o.y = pk2(f0.z, f0.w);
        o.z = pk2(f1.x, f1.y); o.w = pk2(f1.z, f1.w);
        *(uint4*)(dst + off) = o;
    } else {
        const int idx = (bid - 9216) * 256 + tid;   // [0,4096)
        const int b = idx & 63;
        const int k16 = idx >> 6;
        const float* p = h0 + (size_t)b * Hq + k16 * 16;
        const float4 f0 = __ldg((const float4*)p);
        const float4 f1 = __ldg((const float4*)(p + 4));
        const float4 f2 = __ldg((const float4*)(p + 8));
        const float4 f3 = __ldg((const float4*)(p + 12));
        uint2* d = ring1 + ((size_t)k16 * 64 + b) * 4;
        d[0] = make_uint2(pk2(f0.x, f0.y), pk2(f2.x, f2.y));
        d[1] = make_uint2(pk2(f0.z, f0.w), pk2(f2.z, f2.w));
        d[2] = make_uint2(pk2(f1.x, f1.y), pk2(f3.x, f3.y));
        d[3] = make_uint2(pk2(f1.z, f1.w), pk2(f3.z, f3.w));
    }
}

// ============================================================================
// Pure-fp16 MMA GEMM (K1/K3), block tile 128x64, k-tile 64, 256 threads.
// ============================================================================
#define APIT 513
#define BPIT 257

__global__ __launch_bounds__(256) void mma_gemm16(
    const __half* __restrict__ A16, const __half* __restrict__ B16,
    const float* __restrict__ bias, float* __restrict__ C,
    int N, int K)
{
    __shared__ __align__(16) uint2 As2[4 * APIT];
    __shared__ __align__(16) uint2 Bs2[4 * BPIT];

    const int tid = threadIdx.x;
    const int m0 = blockIdx.y * 128, n0 = blockIdx.x * 64;
    const int lane = tid & 31, warp = tid >> 5;
    const int g = lane >> 2, q = lane & 3;
    const int wm = warp >> 1, wn = warp & 1;

    const int ap = tid & 3;
    const int ar = tid >> 2;
    size_t arow[2];
#pragma unroll
    for (int i = 0; i < 2; i++) arow[i] = (size_t)(m0 + ar + i * 64) * (size_t)K;
    const size_t brow = (size_t)(n0 + ar) * (size_t)K;

    float acc[2][4][4];
#pragma unroll
    for (int mt = 0; mt < 2; mt++)
#pragma unroll
        for (int nt = 0; nt < 4; nt++)
#pragma unroll
            for (int e = 0; e < 4; e++) acc[mt][nt][e] = 0.0f;

    uint4 ha[2][2], hb[2];
#pragma unroll
    for (int i = 0; i < 2; i++) {
        ha[i][0] = __ldg((const uint4*)(A16 + arow[i] + ap * 16));
        ha[i][1] = __ldg((const uint4*)(A16 + arow[i] + ap * 16 + 8));
    }
    hb[0] = __ldg((const uint4*)(B16 + brow + ap * 16));
    hb[1] = __ldg((const uint4*)(B16 + brow + ap * 16 + 8));

    for (int k0 = 0; k0 < K; k0 += 64) {
#pragma unroll
        for (int i = 0; i < 2; i++) {
            uint2* d = &As2[ap * APIT + (ar + i * 64) * 4];
            d[0] = make_uint2(ha[i][0].x, ha[i][1].x);
            d[1] = make_uint2(ha[i][0].y, ha[i][1].y);
            d[2] = make_uint2(ha[i][0].z, ha[i][1].z);
            d[3] = make_uint2(ha[i][0].w, ha[i][1].w);
        }
        {
            uint2* d = &Bs2[ap * BPIT + ar * 4];
            d[0] = make_uint2(hb[0].x, hb[1].x);
            d[1] = make_uint2(hb[0].y, hb[1].y);
            d[2] = make_uint2(hb[0].z, hb[1].z);
            d[3] = make_uint2(hb[0].w, hb[1].w);
        }
        __syncthreads();

        if (k0 + 64 < K) {
#pragma unroll
            for (int i = 0; i < 2; i++) {
                ha[i][0] = __ldg((const uint4*)(A16 + arow[i] + k0 + 64 + ap * 16));
                ha[i][1] = __ldg((const uint4*)(A16 + arow[i] + k0 + 64 + ap * 16 + 8));
            }
            hb[0] = __ldg((const uint4*)(B16 + brow + k0 + 64 + ap * 16));
            hb[1] = __ldg((const uint4*)(B16 + brow + k0 + 64 + ap * 16 + 8));
        }

#pragma unroll
        for (int p = 0; p < 4; p++) {
            uint2 aLo[2], aHi[2];
#pragma unroll
            for (int mt = 0; mt < 2; mt++) {
                const int r = wm * 32 + mt * 16 + g;
                aLo[mt] = As2[p * APIT + r * 4 + q];
                aHi[mt] = As2[p * APIT + (r + 8) * 4 + q];
            }
#pragma unroll
            for (int nt = 0; nt < 4; nt++) {
                const uint2 bb = Bs2[p * BPIT + (wn * 32 + nt * 8 + g) * 4 + q];
#pragma unroll
                for (int mt = 0; mt < 2; mt++)
                    mma_f16(acc[mt][nt][0], acc[mt][nt][1], acc[mt][nt][2], acc[mt][nt][3],
                            aLo[mt].x, aHi[mt].x, aLo[mt].y, aHi[mt].y, bb.x, bb.y);
            }
        }
        __syncthreads();
    }

#pragma unroll
    for (int mt = 0; mt < 2; mt++) {
        const int mrow = m0 + wm * 32 + mt * 16 + g;
#pragma unroll
        for (int nt = 0; nt < 4; nt++) {
            const int col = n0 + wn * 32 + nt * 8 + 2 * q;
            const float2 bb = *(const float2*)&bias[col];
            float2 o0, o1;
            o0.x = acc[mt][nt][0] + bb.x; o0.y = acc[mt][nt][1] + bb.y;
            o1.x = acc[mt][nt][2] + bb.x; o1.y = acc[mt][nt][3] + bb.y;
            *(float2*)&C[(size_t)mrow * N + col] = o0;
            *(float2*)&C[(size_t)(mrow + 8) * N + col] = o1;
        }
    }
}

// ============================================================================
// Persistent GRU recurrence: no staging (A fragments direct from L2 ring),
// warp-local flag polling, 2 block syncs per step. 64 blocks x 256 threads.
// ============================================================================
#define NB2 64
#define WPLANE 192
#define WS_U2 (64 * WPLANE)
#define REDP 52
#define RED_FLOATS (8 * 32 * REDP)
#define K2_SMEM (WS_U2 * 8 + RED_FLOATS * 4)   // 98304 + 53248 = 151552 B

__global__ __launch_bounds__(256, 1) void gru_rec_mma(
    const float* __restrict__ xp, const float* __restrict__ h0,
    const float* __restrict__ w_hh, const float* __restrict__ b_hh,
    __half* __restrict__ hs16)
{
    extern __shared__ uint2 sm2[];
    uint2* Ws2 = sm2;                       // resident weights
    float* Redf = (float*)(sm2 + WS_U2);    // k-reduce exchange

    const int tid = threadIdx.x;
    const int lane = tid & 31, warp = tid >> 5;
    const int g = lane >> 2, q = lane & 3;
    const int wk = warp >> 1, wmg = warp & 1;
    const int k16blk = blockIdx.x;          // this block produces k16 plane = blockIdx.x
    const int hc0 = k16blk * 16;

    // resident weights (fp16 pairs)
    for (int idx = tid; idx < WS_U2; idx += 256) {
        const int k16 = idx / WPLANE;
        const int r = idx - k16 * WPLANE;
        const int n = r >> 2, qq = r & 3;
        const float* src = w_hh + ((size_t)(n >> 4) * Hq + hc0 + (n & 15)) * Hq + k16 * 16;
        Ws2[idx] = make_uint2(pk2(src[2 * qq], src[2 * qq + 1]),
                              pk2(src[2 * qq + 8], src[2 * qq + 9]));
    }

    // gate ownership: thread -> b = tid>>2, cols hc0 + (tid&3)*4 + [0..3]
    const int gb = tid >> 2;
    const int gc = tid & 3;
    const int gc4 = gc * 4;
    const float4 bhr4 = *(const float4*)&b_hh[hc0 + gc4];
    const float4 bhz4 = *(const float4*)&b_hh[Hq + hc0 + gc4];
    const float4 bhn4 = *(const float4*)&b_hh[2 * Hq + hc0 + gc4];
    float4 h_prev = *(const float4*)&h0[(size_t)gb * Hq + hc0 + gc4];

    // ring u32 slot indices for this thread's two fp16-pairs
    const int slot = gc >> 1;             // .x (0) or .y (1)
    const int qa = (gc & 1) * 2;          // base q
    const int ridx0 = qa * 2 + slot;
    const int ridx1 = (qa + 1) * 2 + slot;

    const unsigned G0 = g_gen2;
    __syncthreads();

    for (int t = 0; t < Tq; t++) {
        const uint2* rbuf = g_hr[(t - 1) & 1];
        uint2* rnew = g_hr[t & 1];

        // xp prefetch (issued before poll; consumed at gates)
        const float* xpb = xp + ((size_t)t * 64 + gb) * Gq + hc0 + gc4;
        const float4 pxr = __ldg((const float4*)xpb);
        const float4 pxz = __ldg((const float4*)(xpb + Hq));
        const float4 pxn = __ldg((const float4*)(xpb + 2 * Hq));

        // ---- warp-local acquire barrier: only this warp's 16 source planes ----
        if (t > 0) {
            const unsigned need = G0 + (unsigned)t;
            if (lane < 16) {
                while (ld_acquire_gpu(&g_flag2[wk * 16 + lane]) < need) { }
            }
            __syncwarp();
        }

        // ---- GEMM: warp = m32 x n48 x k256, A direct from L2 ring ----
        float acc[2][6][4];
#pragma unroll
        for (int mt = 0; mt < 2; mt++)
#pragma unroll
            for (int nt = 0; nt < 6; nt++)
#pragma unroll
                for (int e = 0; e < 4; e++) acc[mt][nt][e] = 0.0f;

        const int kb = wk * 16;
        const int r0 = wmg * 32 + g;
#pragma unroll
        for (int kk = 0; kk < 16; kk++) {
            const uint2* ra = rbuf + (size_t)(kb + kk) * 256;
            uint2 aLo[2], aHi[2];
#pragma unroll
            for (int mt = 0; mt < 2; mt++) {
                aLo[mt] = ldcg_u2(ra + (r0 + mt * 16) * 4 + q);
                aHi[mt] = ldcg_u2(ra + (r0 + mt * 16 + 8) * 4 + q);
            }
            const uint2* wp = Ws2 + (size_t)(kb + kk) * WPLANE;
#pragma unroll
            for (int nt = 0; nt < 6; nt++) {
                const uint2 bb = wp[(nt * 8 + g) * 4 + q];
#pragma unroll
                for (int mt = 0; mt < 2; mt++)
                    mma_f16(acc[mt][nt][0], acc[mt][nt][1], acc[mt][nt][2], acc[mt][nt][3],
                            aLo[mt].x, aHi[mt].x, aLo[mt].y, aHi[mt].y, bb.x, bb.y);
            }
        }

        // ---- all warps publish partials (own smem region, no pre-sync needed) ----
        {
            float* red = Redf + (wk * 2 + wmg) * (32 * REDP);
#pragma unroll
            for (int mt = 0; mt < 2; mt++) {
                const int rr = mt * 16 + g;
#pragma unroll
                for (int nt = 0; nt < 6; nt++) {
                    *(float2*)&red[rr * REDP + nt * 8 + 2 * q] =
                        make_float2(acc[mt][nt][0], acc[mt][nt][1]);
                    *(float2*)&red[(rr + 8) * REDP + nt * 8 + 2 * q] =
                        make_float2(acc[mt][nt][2], acc[mt][nt][3]);
                }
            }
        }
        __syncthreads();

        // ---- per-thread reduce + gates (4 outputs) ----
        {
            const int half = gb >> 5;
            const int rr = gb & 31;
            float sr[4] = {0, 0, 0, 0}, sz[4] = {0, 0, 0, 0}, sn[4] = {0, 0, 0, 0};
#pragma unroll
            for (int k4 = 0; k4 < 4; k4++) {
                const float* red = Redf + (k4 * 2 + half) * (32 * REDP) + rr * REDP;
                const float4 vr = *(const float4*)&red[0 * 16 + gc4];
                const float4 vz = *(const float4*)&red[1 * 16 + gc4];
                const float4 vn = *(const float4*)&red[2 * 16 + gc4];
                sr[0] += vr.x; sr[1] += vr.y; sr[2] += vr.z; sr[3] += vr.w;
                sz[0] += vz.x; sz[1] += vz.y; sz[2] += vz.z; sz[3] += vz.w;
                sn[0] += vn.x; sn[1] += vn.y; sn[2] += vn.z; sn[3] += vn.w;
            }
            const float pxr_[4] = {pxr.x, pxr.y, pxr.z, pxr.w};
            const float pxz_[4] = {pxz.x, pxz.y, pxz.z, pxz.w};
            const float pxn_[4] = {pxn.x, pxn.y, pxn.z, pxn.w};
            const float bhr_[4] = {bhr4.x, bhr4.y, bhr4.z, bhr4.w};
            const float bhz_[4] = {bhz4.x, bhz4.y, bhz4.z, bhz4.w};
            const float bhn_[4] = {bhn4.x, bhn4.y, bhn4.z, bhn4.w};
            float hp_[4] = {h_prev.x, h_prev.y, h_prev.z, h_prev.w};
            float hv[4];
#pragma unroll
            for (int e = 0; e < 4; e++) {
                const float r = sigm_fast(pxr_[e] + sr[e] + bhr_[e]);
                const float z = sigm_fast(pxz_[e] + sz[e] + bhz_[e]);
                const float nn = tanh_fast(pxn_[e] + r * (sn[e] + bhn_[e]));
                hv[e] = (1.0f - z) * nn + z * hp_[e];
            }
            h_prev = make_float4(hv[0], hv[1], hv[2], hv[3]);
            const unsigned p0 = pk2(hv[0], hv[1]);
            const unsigned p1 = pk2(hv[2], hv[3]);
            // ring (fragment layout) — this block owns plane k16blk
            unsigned* rb32 = (unsigned*)(rnew + ((size_t)k16blk * 64 + gb) * 4);
            rb32[ridx0] = p0;
            rb32[ridx1] = p1;
            // history (row-major, fp16)
            *(uint2*)(hs16 + ((size_t)gb * Tq + t) * Hq + hc0 + gc4) = make_uint2(p0, p1);
        }

        // ---- release publish ----
        __syncthreads();
        if (tid == 0) st_release_gpu(&g_flag2[blockIdx.x], G0 + (unsigned)t + 1u);
    }

    if (blockIdx.x == 0 && tid == 0) {
        __threadfence();
        g_gen2 = G0 + (unsigned)Tq;
    }
}

__global__ void copy_hlast_kernel(const __half* __restrict__ hs16, float* __restrict__ out)
{
    const int idx = blockIdx.x * 256 + threadIdx.x;
    if (idx < Bq * Hq) {
        const int b = idx >> 10;
        const int h = idx & 1023;
        out[idx] = __half2float(hs16[((size_t)b * Tq + (Tq - 1)) * Hq + h]);
    }
}

// ============================================================================
extern "C" void kernel_launch(void* const* d_in, const int* in_sizes, int n_in,
                              void* d_out, int out_size)
{
    const float* inputs = (const float*)d_in[0];
    const float* h0     = (const float*)d_in[1];
    const float* w_ih   = (const float*)d_in[2];
    const float* w_hh   = (const float*)d_in[3];
    const float* b_ih   = (const float*)d_in[4];
    const float* b_hh   = (const float*)d_in[5];
    const float* w_out  = (const float*)d_in[6];
    const float* b_out  = (const float*)d_in[7];
    float* out = (float*)d_out;

    float* xp;
    __half *hs16, *x16, *wih16, *wout16;
    uint2* hr;
    cudaGetSymbolAddress((void**)&xp, g_xp);
    cudaGetSymbolAddress((void**)&hs16, g_hs16);
    cudaGetSymbolAddress((void**)&x16, g_x16);
    cudaGetSymbolAddress((void**)&wih16, g_wih16);
    cudaGetSymbolAddress((void**)&wout16, g_wout16);
    cudaGetSymbolAddress((void**)&hr, g_hr);

    // keep gru_rec_mma at overall launch #4 (where the profiler lands)
    noop_kernel<<<1, 32>>>();

    // all conversions in one kernel (x16 | weights | h0 -> ring buf 1)
    cvt_all_kernel<<<9232, 256>>>(inputs, w_ih, w_out, h0,
                                  x16, wih16, wout16, hr + 64 * 64 * 4);

    // K1: x_proj
    {
        dim3 grid(Gq / 64, (Tq * Bq) / 128);
        mma_gemm16<<<grid, 256>>>(x16, wih16, b_ih, xp, Gq, Iq);
    }

    // K2: persistent GRU recurrence
    cudaFuncSetAttribute(gru_rec_mma, cudaFuncAttributeMaxDynamicSharedMemorySize, K2_SMEM);
    gru_rec_mma<<<NB2, 256, K2_SMEM>>>(xp, h0, w_hh, b_hh, hs16);

    // K3: out = hs16 @ wout16^T + b_out
    {
        dim3 grid(Oq / 64, (Bq * Tq) / 128);
        mma_gemm16<<<grid, 256>>>(hs16, wout16, b_out, out, Oq, Hq);
    }

    // K4: h_last tail
    copy_hlast_kernel<<<(Bq * Hq) / 256, 256>>>(hs16, out + (size_t)Bq * Tq * Oq);
}